// round 14
// baseline (speedup 1.0000x reference)
#include <cuda_runtime.h>
#include <cuda_bf16.h>
#include <cstdint>
#include <math.h>

// ---------------------------------------------------------------------------
// stack_latent_attention (B=16, NV=NH=D=1024)
// GEMMs via mma.sync.m16n8k16 bf16, split-bf16 3-term (hh + hl + lh).
// R14: 256 thr / 64x32 warp tile / BK=64 / 3-stage cp.async  +
//      register double-buffered fragments: LDSMs for phase kk+1 issue before
//      the MMAs of phase kk, overlapping crossbar with tensor pipe
//      (profiled phase-serialization bubble = 37% of GEMM cycles).
// ---------------------------------------------------------------------------

#define BB    16
#define NVV   1024
#define DD    1024
#define MROWS (BB * NVV)
#define KVZ   (3 * DD)                 // 3072
#define NEGV  (-1e30f)

// ============================ PTX helpers ===================================
__device__ __forceinline__ uint32_t smem_u32(const void* p) {
    uint32_t a;
    asm("{ .reg .u64 t; cvta.to.shared.u64 t, %1; cvt.u32.u64 %0, t; }"
        : "=r"(a) : "l"(p));
    return a;
}

#define CP16(s, g) \
    asm volatile("cp.async.cg.shared.global [%0], [%1], 16;" \
                 :: "r"(s), "l"(g) : "memory")

#define LDSM4(r, addr) \
    asm volatile("ldmatrix.sync.aligned.m8n8.x4.shared.b16 {%0,%1,%2,%3}, [%4];" \
                 : "=r"((r)[0]), "=r"((r)[1]), "=r"((r)[2]), "=r"((r)[3]) \
                 : "r"(addr))

#define MMA(c, a, b0, b1) \
    asm volatile("mma.sync.aligned.m16n8k16.row.col.f32.bf16.bf16.f32 " \
                 "{%0,%1,%2,%3}, {%4,%5,%6,%7}, {%8,%9}, {%0,%1,%2,%3};" \
                 : "+f"((c)[0]), "+f"((c)[1]), "+f"((c)[2]), "+f"((c)[3]) \
                 : "r"((a)[0]), "r"((a)[1]), "r"((a)[2]), "r"((a)[3]), \
                   "r"(b0), "r"(b1))

// ============================ scratch =======================================
__device__ __align__(256) __nv_bfloat16 g_vzhi[(long long)MROWS * KVZ];
__device__ __align__(256) __nv_bfloat16 g_vzlo[(long long)MROWS * KVZ];
__device__ __align__(256) __nv_bfloat16 g_Wvzh[DD * KVZ], g_Wvzl[DD * KVZ];
__device__ __align__(256) __nv_bfloat16 g_hhi[MROWS * DD], g_hlo[MROWS * DD];
__device__ __align__(256) __nv_bfloat16 g_Whh[DD * DD], g_Whl[DD * DD];
__device__ __align__(256) __nv_bfloat16 g_qvTh[DD * DD], g_qvTl[DD * DD];
__device__ __align__(256) __nv_bfloat16 g_khTh[DD * DD], g_khTl[DD * DD];
__device__ __align__(256) __nv_bfloat16 g_WTh[DD * DD],  g_WTl[DD * DD];
__device__ __align__(256) __nv_bfloat16 g_vWh[MROWS * DD], g_vWl[MROWS * DD];
__device__ __align__(256) __nv_bfloat16 g_Ph[MROWS * DD],  g_Pl[MROWS * DD];
__device__ __align__(256) __nv_bfloat16 g_HTh[MROWS * DD], g_HTl[MROWS * DD];
__device__ __align__(256) float g_VZ[MROWS * DD];
__device__ __align__(256) float g_att[(long long)BB * NVV * NVV];
__device__ __align__(256) float g_Hv[MROWS * DD];
__device__ float g_c[DD];
__device__ float g_t[MROWS];
__device__ float g_u[MROWS];
__device__ float g_p[MROWS];
__device__ float g_g[BB * DD];

// ============================ megaconv ======================================
#define MC_V   16384
#define MC_Z   (MC_V + 32768)
#define MC_WV  (MC_Z + 1024)
#define MC_WZ  (MC_WV + 2048)
#define MC_H   (MC_WZ + 16384)
#define MC_WH  (MC_H + 1024)
#define MC_QT  (MC_WH + 1024)
#define MC_KT  (MC_QT + 1024)
#define MC_GRID MC_KT

__global__ __launch_bounds__(256)
void megaconv(const float* __restrict__ v,  const float* __restrict__ z,
              const float* __restrict__ Wv, const float* __restrict__ Wz,
              const float* __restrict__ h,  const float* __restrict__ Wh,
              const float* __restrict__ qv, const float* __restrict__ kh,
              __nv_bfloat16* __restrict__ vzh,  __nv_bfloat16* __restrict__ vzl,
              __nv_bfloat16* __restrict__ Wvzh, __nv_bfloat16* __restrict__ Wvzl,
              __nv_bfloat16* __restrict__ hh,   __nv_bfloat16* __restrict__ hl,
              __nv_bfloat16* __restrict__ Whh,  __nv_bfloat16* __restrict__ Whl,
              __nv_bfloat16* __restrict__ qvTh, __nv_bfloat16* __restrict__ qvTl,
              __nv_bfloat16* __restrict__ khTh, __nv_bfloat16* __restrict__ khTl)
{
    __shared__ float ts[32][33];
    const int b = blockIdx.x;
    const int tid = threadIdx.x;

    if (b < MC_WH) {
        const float* src; __nv_bfloat16 *dh, *dl;
        long long i4, dst;
        if (b < MC_V) {
            i4 = (long long)b * 256 + tid;
            long long p = i4 << 2;
            src = v; dh = vzh; dl = vzl;
            dst = (p >> 10) * KVZ + (p & 1023);
        } else if (b < MC_Z) {
            i4 = (long long)(b - MC_V) * 256 + tid;
            long long p = i4 << 2;
            src = z; dh = vzh; dl = vzl;
            dst = (p >> 11) * KVZ + 1024 + (p & 2047);
        } else if (b < MC_WV) {
            i4 = (long long)(b - MC_Z) * 256 + tid;
            long long p = i4 << 2;
            src = Wv; dh = Wvzh; dl = Wvzl;
            dst = (p >> 10) * KVZ + (p & 1023);
        } else if (b < MC_WZ) {
            i4 = (long long)(b - MC_WV) * 256 + tid;
            long long p = i4 << 2;
            src = Wz; dh = Wvzh; dl = Wvzl;
            dst = (p >> 11) * KVZ + 1024 + (p & 2047);
        } else if (b < MC_H) {
            i4 = (long long)(b - MC_WZ) * 256 + tid;
            src = h; dh = hh; dl = hl;
            dst = i4 << 2;
        } else {
            i4 = (long long)(b - MC_H) * 256 + tid;
            src = Wh; dh = Whh; dl = Whl;
            dst = i4 << 2;
        }
        float4 f = ((const float4*)src)[i4];
        __nv_bfloat16 hb[4], lb[4];
        float e[4] = {f.x, f.y, f.z, f.w};
#pragma unroll
        for (int k = 0; k < 4; k++) {
            hb[k] = __float2bfloat16(e[k]);
            lb[k] = __float2bfloat16(e[k] - __bfloat162float(hb[k]));
        }
        *(uint2*)(dh + dst) = *(uint2*)hb;
        *(uint2*)(dl + dst) = *(uint2*)lb;
    } else {
        int tb = b - MC_WH;
        const float* src; __nv_bfloat16 *dh, *dl;
        if (tb < 1024) { src = qv; dh = qvTh; dl = qvTl; }
        else           { tb -= 1024; src = kh; dh = khTh; dl = khTl; }
        const int r0 = (tb >> 5) * 32, c0 = (tb & 31) * 32;
        const int tx = tid & 31, ty = tid >> 5;
        for (int i = ty; i < 32; i += 8)
            ts[i][tx] = src[(long long)(r0 + i) * DD + c0 + tx];
        __syncthreads();
        for (int i = ty; i < 32; i += 8) {
            float val = ts[tx][i];
            __nv_bfloat16 hbf = __float2bfloat16(val);
            long long o = (long long)(c0 + i) * DD + r0 + tx;
            dh[o] = hbf;
            dl[o] = __float2bfloat16(val - __bfloat162float(hbf));
        }
    }
}

// ============================ mma.sync GEMM =================================
// C[M,N] = sum_k (Ah+Al)[m,k] * (Bh+Bl)[n,k]  (dropping Al*Bl)
// CTA tile 128x128, BK=64, 3-stage cp.async (depth-2 prefetch), 256 threads.
// 8 warps as 2(M) x 4(N); warp tile 64x32.
// Register double-buffered fragments: phase kk+1 LDSMs issue before phase-kk
// MMAs, so crossbar overlaps tensor pipe.
#define BM    128
#define BN    128
#define BKC   64
#define PADK  72                        // row stride in bf16 elems (144 B)
#define ROWB  (PADK * 2)                // 144 bytes
#define ARR   (BM * ROWB)               // 18432 B per operand array
#define STAGE (4 * ARR)                 // Ah | Al | Bh | Bl = 73728 B
#define NSTG  3
#define SMEM_GEMM (NSTG * STAGE)        // 221184 B

__global__ __launch_bounds__(256)
void gemm_split(const __nv_bfloat16* __restrict__ Ahi, const __nv_bfloat16* __restrict__ Alo,
                const __nv_bfloat16* __restrict__ Bhi, const __nv_bfloat16* __restrict__ Blo,
                const float* __restrict__ bias, const int* __restrict__ colmask,
                float* __restrict__ Cf,
                __nv_bfloat16* __restrict__ Chi, __nv_bfloat16* __restrict__ Clo,
                int K, int lda, int ldb, int ldc, int transOut,
                long long sA, long long sB, long long sC, long long sBias)
{
    extern __shared__ char smem[];
    const uint32_t sb = smem_u32(smem);
    const int tid = threadIdx.x;
    const int bz = blockIdx.z;
    Ahi += (long long)bz * sA;  Alo += (long long)bz * sA;
    Bhi += (long long)bz * sB;  Blo += (long long)bz * sB;
    if (bias)    bias    += (long long)bz * sBias;
    if (colmask) colmask += (long long)bz * NVV;
    const long long coff = (long long)bz * sC;
    const int m0 = blockIdx.y * BM;
    const int n0 = blockIdx.x * BN;

    const int lane = tid & 31, wid = tid >> 5;
    const int wm0 = (wid >> 2) * 64;      // 0 / 64
    const int wn0 = (wid & 3) * 32;       // 0 / 32 / 64 / 96

    float acc[4][4][4];
#pragma unroll
    for (int i = 0; i < 4; i++)
#pragma unroll
        for (int j = 0; j < 4; j++)
#pragma unroll
            for (int k = 0; k < 4; k++) acc[i][j][k] = 0.f;

    const int a_row = lane & 15;
    const int a_k   = (lane >> 4) << 3;
    const int b_row = (lane & 7) + ((lane >> 1) & 8);
    const int b_k   = ((lane >> 3) & 1) << 3;

    const int nIter = K >> 6;             // BK=64

    auto load_stage = [&](int it, int s) {
        const long long k0 = (long long)it * BKC;
        const uint32_t st = sb + s * STAGE;
#pragma unroll
        for (int j = 0; j < 4; j++) {
            int idx = tid + j * 256;            // 0..1023
            int r = idx >> 3, c = idx & 7;
            uint32_t so = r * ROWB + c * 16;
            long long ga = (long long)(m0 + r) * lda + k0 + c * 8;
            long long gb = (long long)(n0 + r) * ldb + k0 + c * 8;
            CP16(st + 0 * ARR + so, (const char*)(Ahi + ga));
            CP16(st + 1 * ARR + so, (const char*)(Alo + ga));
            CP16(st + 2 * ARR + so, (const char*)(Bhi + gb));
            CP16(st + 3 * ARR + so, (const char*)(Blo + gb));
        }
        asm volatile("cp.async.commit_group;" ::: "memory");
    };

    load_stage(0, 0);
    if (nIter > 1) load_stage(1, 1);

    int slot = 0;
    for (int it = 0; it < nIter; ++it) {
        asm volatile("cp.async.wait_group 1;" ::: "memory");
        __syncthreads();
        if (it + 2 < nIter) {
            int ns = slot + 2; if (ns >= NSTG) ns -= NSTG;
            load_stage(it + 2, ns);
        } else {
            asm volatile("cp.async.commit_group;" ::: "memory");
        }

        const uint32_t st = sb + slot * STAGE;

        // double-buffered register fragments
        uint32_t ah[2][4][4], al[2][4][4], bh[2][2][4], bl[2][2][4];

        auto ldfrag = [&](int kk, int bf) {
#pragma unroll
            for (int mt = 0; mt < 4; mt++) {
                uint32_t ad = st + (wm0 + 16 * mt + a_row) * ROWB + (kk + a_k) * 2;
                LDSM4(ah[bf][mt], ad);
                LDSM4(al[bf][mt], ad + ARR);
            }
#pragma unroll
            for (int gq = 0; gq < 2; gq++) {
                uint32_t bd = st + 2 * ARR
                            + (wn0 + gq * 16 + b_row) * ROWB + (kk + b_k) * 2;
                LDSM4(bh[bf][gq], bd);
                LDSM4(bl[bf][gq], bd + ARR);
            }
        };

        ldfrag(0, 0);
#pragma unroll
        for (int p4 = 0; p4 < 4; p4++) {
            const int cur = p4 & 1;
            if (p4 < 3) ldfrag((p4 + 1) * 16, cur ^ 1);  // prefetch next phase
            // term 1: Ah * Bh
#pragma unroll
            for (int mt = 0; mt < 4; mt++)
#pragma unroll
                for (int nt = 0; nt < 4; nt++)
                    MMA(acc[mt][nt], ah[cur][mt],
                        bh[cur][nt >> 1][(nt & 1) * 2],
                        bh[cur][nt >> 1][(nt & 1) * 2 + 1]);
            // term 2: Ah * Bl
#pragma unroll
            for (int mt = 0; mt < 4; mt++)
#pragma unroll
                for (int nt = 0; nt < 4; nt++)
                    MMA(acc[mt][nt], ah[cur][mt],
                        bl[cur][nt >> 1][(nt & 1) * 2],
                        bl[cur][nt >> 1][(nt & 1) * 2 + 1]);
            // term 3: Al * Bh
#pragma unroll
            for (int mt = 0; mt < 4; mt++)
#pragma unroll
                for (int nt = 0; nt < 4; nt++)
                    MMA(acc[mt][nt], al[cur][mt],
                        bh[cur][nt >> 1][(nt & 1) * 2],
                        bh[cur][nt >> 1][(nt & 1) * 2 + 1]);
        }
        if (++slot == NSTG) slot = 0;
    }

    const int g2 = lane >> 2;
    const int t2 = (lane & 3) * 2;

    if (transOut) {
        // ---- transposed split-bf16 epilogue: T[b, n, m] (b from m0) ----
        __syncthreads();                      // smem reuse: all LDSMs done
        float* stage = (float*)smem;          // [BM][BN+1] = 66048 B
        const int LDS_ = BN + 1;
#pragma unroll
        for (int mt = 0; mt < 4; mt++)
#pragma unroll
            for (int hf = 0; hf < 2; hf++) {
                int row = wm0 + mt * 16 + g2 + hf * 8;
#pragma unroll
                for (int nt = 0; nt < 4; nt++) {
                    int col = wn0 + nt * 8 + t2;
                    stage[row * LDS_ + col]     = acc[mt][nt][hf * 2 + 0];
                    stage[row * LDS_ + col + 1] = acc[mt][nt][hf * 2 + 1];
                }
            }
        __syncthreads();
        const int b = m0 >> 10, tok0 = m0 & 1023;
#pragma unroll 4
        for (int i = 0; i < (BM * BN) / 256; i++) {   // 64 iters
            int idx = i * 256 + tid;
            int m = idx & (BM - 1), n = idx >> 7;
            float val = stage[m * LDS_ + n];
            __nv_bfloat16 hbf = __float2bfloat16(val);
            long long o = ((long long)b << 20) + ((long long)(n0 + n) << 10)
                        + tok0 + m;
            Chi[o] = hbf;
            Clo[o] = __float2bfloat16(val - __bfloat162float(hbf));
        }
        return;
    }

    // ---------------------------- epilogue ---------------------------------
#pragma unroll
    for (int mt = 0; mt < 4; mt++) {
#pragma unroll
        for (int hf = 0; hf < 2; hf++) {
            int row = m0 + wm0 + mt * 16 + g2 + hf * 8;
#pragma unroll
            for (int nt = 0; nt < 4; nt++) {
                int col = n0 + wn0 + nt * 8 + t2;
                float v0 = acc[mt][nt][hf * 2 + 0];
                float v1 = acc[mt][nt][hf * 2 + 1];
                if (bias) { v0 += __ldg(bias + col); v1 += __ldg(bias + col + 1); }
                if (colmask) {
                    if (__ldg(colmask + col) == 0)     v0 = NEGV;
                    if (__ldg(colmask + col + 1) == 0) v1 = NEGV;
                }
                long long o = coff + (long long)row * ldc + col;
                if (Cf) {
                    float2 w; w.x = v0; w.y = v1;
                    *(float2*)(Cf + o) = w;
                } else {
                    __nv_bfloat16 h0 = __float2bfloat16(v0);
                    __nv_bfloat16 h1 = __float2bfloat16(v1);
                    __nv_bfloat16 l0 = __float2bfloat16(v0 - __bfloat162float(h0));
                    __nv_bfloat16 l1 = __float2bfloat16(v1 - __bfloat162float(h1));
                    __nv_bfloat162 hh; hh.x = h0; hh.y = h1;
                    __nv_bfloat162 ll; ll.x = l0; ll.y = l1;
                    *(__nv_bfloat162*)(Chi + o) = hh;
                    *(__nv_bfloat162*)(Clo + o) = ll;
                }
            }
        }
    }
}

// ===================== softmax (writes split-bf16 P) ========================
__global__ __launch_bounds__(256)
void softmax_split_kernel(const float* __restrict__ att,
                          __nv_bfloat16* __restrict__ Ph,
                          __nv_bfloat16* __restrict__ Pl)
{
    __shared__ float red[256];
    __shared__ float ev[NVV];
    const int row = blockIdx.x;
    const float* a = att + (long long)row * NVV;
    const int tid = threadIdx.x;

    float mx = -INFINITY;
    for (int c = tid; c < NVV; c += 256) mx = fmaxf(mx, a[c]);
    red[tid] = mx; __syncthreads();
    for (int s = 128; s > 0; s >>= 1) {
        if (tid < s) red[tid] = fmaxf(red[tid], red[tid + s]);
        __syncthreads();
    }
    mx = red[0]; __syncthreads();

    float sum = 0.f;
    for (int c = tid; c < NVV; c += 256) {
        float e = __expf(a[c] - mx);
        ev[c] = e;
        sum += e;
    }
    red[tid] = sum; __syncthreads();
    for (int s = 128; s > 0; s >>= 1) {
        if (tid < s) red[tid] += red[tid + s];
        __syncthreads();
    }
    float inv = 1.f / red[0];
    for (int c = tid; c < NVV; c += 256) {
        float v = ev[c] * inv;
        __nv_bfloat16 h = __float2bfloat16(v);
        long long o = (long long)row * NVV + c;
        Ph[o] = h;
        Pl[o] = __float2bfloat16(v - __bfloat162float(h));
    }
}

// ================ c[e] = sum_d kh_w[d,e] * qv_b[d]  (fp32) ==================
__global__ __launch_bounds__(256)
void c_kernel(const float* __restrict__ kh_w, const float* __restrict__ qv_b,
              float* __restrict__ c)
{
    int e = blockIdx.x * 256 + threadIdx.x;
    float acc = 0.f;
#pragma unroll 4
    for (int d = 0; d < DD; d++)
        acc = fmaf(kh_w[(long long)d * DD + e], qv_b[d], acc);
    c[e] = acc;
}

// ================= t[row] = h[row,:] . c  (per-key att bias) ================
__global__ __launch_bounds__(256)
void t_kernel(const float* __restrict__ h, const float* __restrict__ c,
              float* __restrict__ t)
{
    __shared__ float red[256];
    const int row = blockIdx.x;
    const int tid = threadIdx.x;
    const float* hr = h + (long long)row * DD;
    float4 a = *(const float4*)(hr + tid * 4);
    float4 w = *(const float4*)(c + tid * 4);
    float acc = a.x * w.x + a.y * w.y + a.z * w.z + a.w * w.w;
    red[tid] = acc; __syncthreads();
    for (int st = 128; st > 0; st >>= 1) {
        if (tid < st) red[tid] += red[tid + st];
        __syncthreads();
    }
    if (tid == 0) t[row] = red[0];
}

// ====== fused: s = sigmoid(VZ + Hv) -> z_new[:, :D]; u = s.Wu ==============
__global__ __launch_bounds__(256)
void su_kernel(const float* __restrict__ VZ, const float* __restrict__ Hv,
               const float* __restrict__ Wu,
               float* __restrict__ zout, float* __restrict__ u)
{
    __shared__ float red[256];
    const int row = blockIdx.x;
    const int tid = threadIdx.x;
    const long long base = (long long)row * DD + tid * 4;
    float4 a = *(const float4*)(VZ + base);
    float4 b = *(const float4*)(Hv + base);
    float4 w = *(const float4*)(Wu + tid * 4);
    float4 s;
    s.x = 1.f / (1.f + __expf(-(a.x + b.x)));
    s.y = 1.f / (1.f + __expf(-(a.y + b.y)));
    s.z = 1.f / (1.f + __expf(-(a.z + b.z)));
    s.w = 1.f / (1.f + __expf(-(a.w + b.w)));
    *(float4*)(zout + (long long)row * 2048 + tid * 4) = s;
    float acc = s.x * w.x + s.y * w.y + s.z * w.z + s.w * w.w;
    red[tid] = acc; __syncthreads();
    for (int st = 128; st > 0; st >>= 1) {
        if (tid < st) red[tid] += red[tid + st];
        __syncthreads();
    }
    if (tid == 0) u[row] = red[0];
}

__global__ __launch_bounds__(256)
void p_kernel(const float* __restrict__ u, const int* __restrict__ v_mask,
              float* __restrict__ p)
{
    __shared__ float red[256];
    __shared__ float vals[NVV];
    const int b = blockIdx.x;
    const int tid = threadIdx.x;

    float mx = -INFINITY;
    for (int j = tid; j < NVV; j += 256) {
        float val = (v_mask[b * NVV + j] == 0) ? NEGV : u[b * NVV + j];
        vals[j] = val;
        mx = fmaxf(mx, val);
    }
    red[tid] = mx; __syncthreads();
    for (int s = 128; s > 0; s >>= 1) {
        if (tid < s) red[tid] = fmaxf(red[tid], red[tid + s]);
        __syncthreads();
    }
    mx = red[0]; __syncthreads();

    float sum = 0.f;
    for (int j = tid; j < NVV; j += 256) {
        float e = __expf(vals[j] - mx);
        vals[j] = e;
        sum += e;
    }
    red[tid] = sum; __syncthreads();
    for (int s = 128; s > 0; s >>= 1) {
        if (tid < s) red[tid] += red[tid + s];
        __syncthreads();
    }
    float inv = 1.f / red[0];
    for (int j = tid; j < NVV; j += 256) p[b * NVV + j] = vals[j] * inv;
}

__global__ __launch_bounds__(256)
void g_kernel(const float* __restrict__ p, const float* __restrict__ v,
              float* __restrict__ g)
{
    __shared__ float ps[NVV];
    const int b = blockIdx.y;
    const int tid = threadIdx.x;
    for (int j = tid; j < NVV; j += 256) ps[j] = p[b * NVV + j];
    __syncthreads();
    const int d = blockIdx.x * 256 + tid;
    const float* vb = v + (long long)b * NVV * DD;
    float acc = 0.f;
#pragma unroll 4
    for (int j = 0; j < NVV; j++)
        acc = fmaf(ps[j], vb[(long long)j * DD + d], acc);
    g[b * DD + d] = acc;
}

__global__ __launch_bounds__(256)
void bcast_kernel(const float* __restrict__ g, float* __restrict__ hnew,
                  float* __restrict__ zout)
{
    long long i = (long long)blockIdx.x * 256 + threadIdx.x;
    int d = (int)(i & 1023);
    long long bi = i >> 10;
    int b = (int)(bi >> 10);
    float val = g[b * DD + d];
    hnew[i] = val;
    zout[bi * 2048 + DD + d] = val;
}

// ================================ launch ====================================
extern "C" void kernel_launch(void* const* d_in, const int* in_sizes, int n_in,
                              void* d_out, int out_size)
{
    const float* v      = (const float*)d_in[0];
    const float* h      = (const float*)d_in[1];
    const float* z      = (const float*)d_in[2];
    const int*   v_mask = (const int*)  d_in[3];
    const int*   h_mask = (const int*)  d_in[4];
    const float* Wv_w   = (const float*)d_in[5];
    const float* Wv_b   = (const float*)d_in[6];
    const float* Wh_w   = (const float*)d_in[7];
    const float* qv_w   = (const float*)d_in[8];
    const float* qv_b   = (const float*)d_in[9];
    const float* kh_w   = (const float*)d_in[10];
    const float* Wz_w   = (const float*)d_in[11];
    const float* Wu_w   = (const float*)d_in[12];

    float* out  = (float*)d_out;
    float* hnew = out;
    float* zout = out + (long long)MROWS * DD;

    cudaFuncSetAttribute(gemm_split, cudaFuncAttributeMaxDynamicSharedMemorySize,
                         SMEM_GEMM);

#define SYM(p, s) do { void* _t; cudaGetSymbolAddress(&_t, s); p = (decltype(p))_t; } while (0)
    __nv_bfloat16 *vzh, *vzl, *Wvzh, *Wvzl, *hhi, *hlo, *Whh, *Whl;
    __nv_bfloat16 *qvTh, *qvTl, *khTh, *khTl, *WTh, *WTl;
    __nv_bfloat16 *vWh, *vWl, *Ph, *Pl, *HTh, *HTl;
    float *VZ, *Att, *Hv, *C, *T, *U, *P, *G;
    SYM(vzh, g_vzhi); SYM(vzl, g_vzlo);
    SYM(Wvzh, g_Wvzh); SYM(Wvzl, g_Wvzl);
    SYM(hhi, g_hhi); SYM(hlo, g_hlo);
    SYM(Whh, g_Whh); SYM(Whl, g_Whl);
    SYM(qvTh, g_qvTh); SYM(qvTl, g_qvTl);
    SYM(khTh, g_khTh); SYM(khTl, g_khTl);
    SYM(WTh, g_WTh); SYM(WTl, g_WTl);
    SYM(vWh, g_vWh); SYM(vWl, g_vWl);
    SYM(Ph, g_Ph); SYM(Pl, g_Pl); SYM(HTh, g_HTh); SYM(HTl, g_HTl);
    SYM(VZ, g_VZ); SYM(Att, g_att); SYM(Hv, g_Hv);
    SYM(C, g_c); SYM(T, g_t); SYM(U, g_u); SYM(P, g_p); SYM(G, g_g);
#undef SYM

    const long long PB = (long long)NVV * NVV;
    dim3 gBig(DD / BN, MROWS / BM, 1);     // (8,128,1)
    dim3 gBat(DD / BN, NVV / BM, BB);      // (8,8,16)
    dim3 gW  (DD / BN, DD / BM, 1);        // (8,8,1)

    // 1: all conversions in one launch
    megaconv<<<MC_GRID, 256>>>(v, z, Wv_w, Wz_w, h, Wh_w, qv_w, kh_w,
                               vzh, vzl, Wvzh, Wvzl, hhi, hlo, Whh, Whl,
                               qvTh, qvTl, khTh, khTl);
    // 2,3: attention bias prep
    c_kernel<<<DD / 256, 256>>>(kh_w, qv_b, C);
    t_kernel<<<MROWS, 256>>>(h, C, T);

    // 4: VZ = [v|z] @ [Wv|Wz]^T + Wv_b   (K=3072)
    gemm_split<<<gBig, 256, SMEM_GEMM>>>(vzh, vzl, Wvzh, Wvzl, Wv_b, nullptr,
                                         VZ, nullptr, nullptr,
                                         KVZ, KVZ, KVZ, DD, 0, 0, 0, 0, 0);
    // 5: HT = (h @ Wh^T)^T  (transOut, split bf16 [b, d, token])
    gemm_split<<<gBig, 256, SMEM_GEMM>>>(hhi, hlo, Whh, Whl, nullptr, nullptr,
                                         nullptr, HTh, HTl,
                                         DD, DD, DD, DD, 1, 0, 0, 0, 0);
    // 6: W = qv_w^T @ kh_w  (transOut -> WT)
    gemm_split<<<gW, 256, SMEM_GEMM>>>(qvTh, qvTl, khTh, khTl, nullptr, nullptr,
                                       nullptr, WTh, WTl,
                                       DD, DD, DD, DD, 1, 0, 0, 0, 0);
    // 7: vW = v @ W   (A = vz columns 0..1023 via lda=3072)
    gemm_split<<<gBig, 256, SMEM_GEMM>>>(vzh, vzl, WTh, WTl, nullptr, nullptr,
                                         nullptr, vWh, vWl,
                                         DD, KVZ, DD, DD, 0, 0, 0, 0, 0);
    // 8: att[b,q,k] = vW[b,q]·h[b,k] + t[b,k]   (h_mask==0 -> NEGV)
    gemm_split<<<gBat, 256, SMEM_GEMM>>>(vWh, vWl, hhi, hlo, T, h_mask,
                                         Att, nullptr, nullptr,
                                         DD, DD, DD, NVV, 0, PB, PB, PB, NVV);
    // 9: softmax -> split P
    softmax_split_kernel<<<MROWS, 256>>>(Att, Ph, Pl);
    // 10: Hv[b,q,d] = sum_k P[b,q,k] * HT[b,d,k]
    gemm_split<<<gBat, 256, SMEM_GEMM>>>(Ph, Pl, HTh, HTl, nullptr, nullptr,
                                         Hv, nullptr, nullptr,
                                         NVV, NVV, NVV, DD, 0, PB, PB, PB, 0);

    // ---- tail ----
    su_kernel<<<MROWS, 256>>>(VZ, Hv, Wu_w, zout, U);
    p_kernel<<<BB, 256>>>(U, v_mask, P);
    g_kernel<<<dim3(DD / 256, BB), 256>>>(P, v, G);
    bcast_kernel<<<(MROWS * DD) / 256, 256>>>(G, hnew, zout);
}

// round 15
// speedup vs baseline: 1.2996x; 1.2996x over previous
#include <cuda_runtime.h>
#include <cuda_fp16.h>
#include <cstdint>
#include <math.h>

// ---------------------------------------------------------------------------
// stack_latent_attention (B=16, NV=NH=D=1024)
// GEMMs via mma.sync.m16n8k16 fp16, 2-term split: C = (Ah+Al)·Bh, fp32 accum.
// A split fp16 (22-bit effective), B single fp16 (error ~2.8e-4 rel).
// R15: 3-term bf16 -> 2-term fp16 (MMA count x2/3, tensor-pipe bound at 63%),
//      4-stage cp.async (depth-3), B-lo buffers eliminated.
// ---------------------------------------------------------------------------

#define BB    16
#define NVV   1024
#define DD    1024
#define MROWS (BB * NVV)
#define KVZ   (3 * DD)                 // 3072
#define NEGV  (-1e30f)

// ============================ PTX helpers ===================================
__device__ __forceinline__ uint32_t smem_u32(const void* p) {
    uint32_t a;
    asm("{ .reg .u64 t; cvta.to.shared.u64 t, %1; cvt.u32.u64 %0, t; }"
        : "=r"(a) : "l"(p));
    return a;
}

#define CP16(s, g) \
    asm volatile("cp.async.cg.shared.global [%0], [%1], 16;" \
                 :: "r"(s), "l"(g) : "memory")

#define LDSM4(r, addr) \
    asm volatile("ldmatrix.sync.aligned.m8n8.x4.shared.b16 {%0,%1,%2,%3}, [%4];" \
                 : "=r"((r)[0]), "=r"((r)[1]), "=r"((r)[2]), "=r"((r)[3]) \
                 : "r"(addr))

#define MMA(c, a, b0, b1) \
    asm volatile("mma.sync.aligned.m16n8k16.row.col.f32.f16.f16.f32 " \
                 "{%0,%1,%2,%3}, {%4,%5,%6,%7}, {%8,%9}, {%0,%1,%2,%3};" \
                 : "+f"((c)[0]), "+f"((c)[1]), "+f"((c)[2]), "+f"((c)[3]) \
                 : "r"((a)[0]), "r"((a)[1]), "r"((a)[2]), "r"((a)[3]), \
                   "r"(b0), "r"(b1))

// ============================ scratch =======================================
__device__ __align__(256) __half g_vzhi[(long long)MROWS * KVZ];
__device__ __align__(256) __half g_vzlo[(long long)MROWS * KVZ];
__device__ __align__(256) __half g_Wvzh[DD * KVZ];
__device__ __align__(256) __half g_hhi[MROWS * DD], g_hlo[MROWS * DD];
__device__ __align__(256) __half g_Whh[DD * DD];
__device__ __align__(256) __half g_qvTh[DD * DD], g_qvTl[DD * DD];
__device__ __align__(256) __half g_khTh[DD * DD];
__device__ __align__(256) __half g_WTh[DD * DD];
__device__ __align__(256) __half g_vWh[MROWS * DD], g_vWl[MROWS * DD];
__device__ __align__(256) __half g_Ph[MROWS * DD],  g_Pl[MROWS * DD];
__device__ __align__(256) __half g_HTh[MROWS * DD];
__device__ __align__(256) float g_VZ[MROWS * DD];
__device__ __align__(256) float g_att[(long long)BB * NVV * NVV];
__device__ __align__(256) float g_Hv[MROWS * DD];
__device__ float g_c[DD];
__device__ float g_t[MROWS];
__device__ float g_u[MROWS];
__device__ float g_p[MROWS];
__device__ float g_g[BB * DD];

// ============================ megaconv ======================================
// One kernel for every fp32 -> fp16 (split or hi-only) conversion:
//   v  -> vz[:, 0:1024] (hi+lo)   z  -> vz[:, 1024:3072] (hi+lo)
//   Wv -> Wvz[:, 0:1024] (hi)     Wz -> Wvz[:, 1024:3072] (hi)
//   h  -> hhi+hlo                 Wh -> Whh (hi)
//   qv_w^T -> qvTh+qvTl           kh_w^T -> khTh (hi)
#define MC_V   16384
#define MC_Z   (MC_V + 32768)
#define MC_WV  (MC_Z + 1024)
#define MC_WZ  (MC_WV + 2048)
#define MC_H   (MC_WZ + 16384)
#define MC_WH  (MC_H + 1024)
#define MC_QT  (MC_WH + 1024)
#define MC_KT  (MC_QT + 1024)
#define MC_GRID MC_KT

__global__ __launch_bounds__(256)
void megaconv(const float* __restrict__ v,  const float* __restrict__ z,
              const float* __restrict__ Wv, const float* __restrict__ Wz,
              const float* __restrict__ h,  const float* __restrict__ Wh,
              const float* __restrict__ qv, const float* __restrict__ kh,
              __half* __restrict__ vzh,  __half* __restrict__ vzl,
              __half* __restrict__ Wvzh,
              __half* __restrict__ hh,   __half* __restrict__ hl,
              __half* __restrict__ Whh,
              __half* __restrict__ qvTh, __half* __restrict__ qvTl,
              __half* __restrict__ khTh)
{
    __shared__ float ts[32][33];
    const int b = blockIdx.x;
    const int tid = threadIdx.x;

    if (b < MC_WH) {
        const float* src; __half *dh, *dl;
        long long i4, dst;
        if (b < MC_V) {
            i4 = (long long)b * 256 + tid;
            long long p = i4 << 2;
            src = v; dh = vzh; dl = vzl;
            dst = (p >> 10) * KVZ + (p & 1023);
        } else if (b < MC_Z) {
            i4 = (long long)(b - MC_V) * 256 + tid;
            long long p = i4 << 2;
            src = z; dh = vzh; dl = vzl;
            dst = (p >> 11) * KVZ + 1024 + (p & 2047);
        } else if (b < MC_WV) {
            i4 = (long long)(b - MC_Z) * 256 + tid;
            long long p = i4 << 2;
            src = Wv; dh = Wvzh; dl = nullptr;
            dst = (p >> 10) * KVZ + (p & 1023);
        } else if (b < MC_WZ) {
            i4 = (long long)(b - MC_WV) * 256 + tid;
            long long p = i4 << 2;
            src = Wz; dh = Wvzh; dl = nullptr;
            dst = (p >> 11) * KVZ + 1024 + (p & 2047);
        } else if (b < MC_H) {
            i4 = (long long)(b - MC_WZ) * 256 + tid;
            src = h; dh = hh; dl = hl;
            dst = i4 << 2;
        } else {
            i4 = (long long)(b - MC_H) * 256 + tid;
            src = Wh; dh = Whh; dl = nullptr;
            dst = i4 << 2;
        }
        float4 f = ((const float4*)src)[i4];
        __half hb[4], lb[4];
        float e[4] = {f.x, f.y, f.z, f.w};
#pragma unroll
        for (int k = 0; k < 4; k++) {
            hb[k] = __float2half(e[k]);
            lb[k] = __float2half(e[k] - __half2float(hb[k]));
        }
        *(uint2*)(dh + dst) = *(uint2*)hb;
        if (dl) *(uint2*)(dl + dst) = *(uint2*)lb;
    } else {
        int tb = b - MC_WH;
        const float* src; __half *dh, *dl;
        if (tb < 1024) { src = qv; dh = qvTh; dl = qvTl; }
        else           { tb -= 1024; src = kh; dh = khTh; dl = nullptr; }
        const int r0 = (tb >> 5) * 32, c0 = (tb & 31) * 32;
        const int tx = tid & 31, ty = tid >> 5;
        for (int i = ty; i < 32; i += 8)
            ts[i][tx] = src[(long long)(r0 + i) * DD + c0 + tx];
        __syncthreads();
        for (int i = ty; i < 32; i += 8) {
            float val = ts[tx][i];
            __half hbf = __float2half(val);
            long long o = (long long)(c0 + i) * DD + r0 + tx;
            dh[o] = hbf;
            if (dl) dl[o] = __float2half(val - __half2float(hbf));
        }
    }
}

// ============================ mma.sync GEMM =================================
// C[M,N] = sum_k (Ah+Al)[m,k] * Bh[n,k]   (fp16 operands, fp32 accum)
// CTA tile 128x128, BK=64, 4-stage cp.async (depth-3 prefetch), 256 threads.
// 8 warps as 2(M) x 4(N); warp tile 64x32.
// bias: per-column fp32 (+ bz*sBias).  colmask: int (+ bz*NVV), 0 -> NEGV.
// transOut=1: write C as fp16 hi (and lo if Clo) transposed [b, n, m].
#define BM    128
#define BN    128
#define BKC   64
#define PADK  72                        // row stride in fp16 elems (144 B)
#define ROWB  (PADK * 2)                // 144 bytes
#define ARR   (BM * ROWB)               // 18432 B per operand array
#define STAGE (3 * ARR)                 // Ah | Al | Bh = 55296 B
#define NSTG  4
#define SMEM_GEMM (NSTG * STAGE)        // 221184 B

__global__ __launch_bounds__(256)
void gemm_split(const __half* __restrict__ Ahi, const __half* __restrict__ Alo,
                const __half* __restrict__ Bhi,
                const float* __restrict__ bias, const int* __restrict__ colmask,
                float* __restrict__ Cf,
                __half* __restrict__ Chi, __half* __restrict__ Clo,
                int K, int lda, int ldb, int ldc, int transOut,
                long long sA, long long sB, long long sC, long long sBias)
{
    extern __shared__ char smem[];
    const uint32_t sb = smem_u32(smem);
    const int tid = threadIdx.x;
    const int bz = blockIdx.z;
    Ahi += (long long)bz * sA;  Alo += (long long)bz * sA;
    Bhi += (long long)bz * sB;
    if (bias)    bias    += (long long)bz * sBias;
    if (colmask) colmask += (long long)bz * NVV;
    const long long coff = (long long)bz * sC;
    const int m0 = blockIdx.y * BM;
    const int n0 = blockIdx.x * BN;

    const int lane = tid & 31, wid = tid >> 5;
    const int wm0 = (wid >> 2) * 64;      // 0 / 64
    const int wn0 = (wid & 3) * 32;       // 0 / 32 / 64 / 96

    float acc[4][4][4];
#pragma unroll
    for (int i = 0; i < 4; i++)
#pragma unroll
        for (int j = 0; j < 4; j++)
#pragma unroll
            for (int k = 0; k < 4; k++) acc[i][j][k] = 0.f;

    const int a_row = lane & 15;
    const int a_k   = (lane >> 4) << 3;
    const int b_row = (lane & 7) + ((lane >> 1) & 8);
    const int b_k   = ((lane >> 3) & 1) << 3;

    const int nIter = K >> 6;             // BK=64

    auto load_stage = [&](int it, int s) {
        const long long k0 = (long long)it * BKC;
        const uint32_t st = sb + s * STAGE;
#pragma unroll
        for (int j = 0; j < 4; j++) {
            int idx = tid + j * 256;            // 0..1023
            int r = idx >> 3, c = idx & 7;
            uint32_t so = r * ROWB + c * 16;
            long long ga = (long long)(m0 + r) * lda + k0 + c * 8;
            long long gb = (long long)(n0 + r) * ldb + k0 + c * 8;
            CP16(st + 0 * ARR + so, (const char*)(Ahi + ga));
            CP16(st + 1 * ARR + so, (const char*)(Alo + ga));
            CP16(st + 2 * ARR + so, (const char*)(Bhi + gb));
        }
        asm volatile("cp.async.commit_group;" ::: "memory");
    };

    load_stage(0, 0);
    if (nIter > 1) load_stage(1, 1);
    if (nIter > 2) load_stage(2, 2);

    int slot = 0;
    for (int it = 0; it < nIter; ++it) {
        asm volatile("cp.async.wait_group 2;" ::: "memory");
        __syncthreads();
        // slot (it+3)%4 held stage it-1, whose reads completed before this
        // barrier -> safe to overwrite.
        if (it + 3 < nIter) {
            int ns = slot + 3; if (ns >= NSTG) ns -= NSTG;
            load_stage(it + 3, ns);
        } else {
            asm volatile("cp.async.commit_group;" ::: "memory");
        }

        const uint32_t st = sb + slot * STAGE;
#pragma unroll
        for (int kk = 0; kk < BKC; kk += 16) {
            uint32_t ah[4][4], al[4][4], bh[2][4];
#pragma unroll
            for (int mt = 0; mt < 4; mt++) {
                uint32_t ad = st + (wm0 + 16 * mt + a_row) * ROWB + (kk + a_k) * 2;
                LDSM4(ah[mt], ad);
                LDSM4(al[mt], ad + ARR);
            }
#pragma unroll
            for (int gq = 0; gq < 2; gq++) {
                uint32_t bd = st + 2 * ARR
                            + (wn0 + gq * 16 + b_row) * ROWB + (kk + b_k) * 2;
                LDSM4(bh[gq], bd);
            }
            // term 1: Ah * Bh
#pragma unroll
            for (int mt = 0; mt < 4; mt++)
#pragma unroll
                for (int nt = 0; nt < 4; nt++)
                    MMA(acc[mt][nt], ah[mt], bh[nt >> 1][(nt & 1) * 2],
                        bh[nt >> 1][(nt & 1) * 2 + 1]);
            // term 2: Al * Bh
#pragma unroll
            for (int mt = 0; mt < 4; mt++)
#pragma unroll
                for (int nt = 0; nt < 4; nt++)
                    MMA(acc[mt][nt], al[mt], bh[nt >> 1][(nt & 1) * 2],
                        bh[nt >> 1][(nt & 1) * 2 + 1]);
        }
        if (++slot == NSTG) slot = 0;
    }

    const int g2 = lane >> 2;
    const int t2 = (lane & 3) * 2;

    if (transOut) {
        // ---- transposed fp16 epilogue: T[b, n, m] (b from m0) ----
        __syncthreads();
        float* stage = (float*)smem;          // [BM][BN+1] = 66048 B
        const int LDS_ = BN + 1;
#pragma unroll
        for (int mt = 0; mt < 4; mt++)
#pragma unroll
            for (int hf = 0; hf < 2; hf++) {
                int row = wm0 + mt * 16 + g2 + hf * 8;
#pragma unroll
                for (int nt = 0; nt < 4; nt++) {
                    int col = wn0 + nt * 8 + t2;
                    stage[row * LDS_ + col]     = acc[mt][nt][hf * 2 + 0];
                    stage[row * LDS_ + col + 1] = acc[mt][nt][hf * 2 + 1];
                }
            }
        __syncthreads();
        const int b = m0 >> 10, tok0 = m0 & 1023;
#pragma unroll 4
        for (int i = 0; i < (BM * BN) / 256; i++) {
            int idx = i * 256 + tid;
            int m = idx & (BM - 1), n = idx >> 7;
            float val = stage[m * LDS_ + n];
            __half hbf = __float2half(val);
            long long o = ((long long)b << 20) + ((long long)(n0 + n) << 10)
                        + tok0 + m;
            Chi[o] = hbf;
            if (Clo) Clo[o] = __float2half(val - __half2float(hbf));
        }
        return;
    }

    // ---------------------------- epilogue ---------------------------------
#pragma unroll
    for (int mt = 0; mt < 4; mt++) {
#pragma unroll
        for (int hf = 0; hf < 2; hf++) {
            int row = m0 + wm0 + mt * 16 + g2 + hf * 8;
#pragma unroll
            for (int nt = 0; nt < 4; nt++) {
                int col = n0 + wn0 + nt * 8 + t2;
                float v0 = acc[mt][nt][hf * 2 + 0];
                float v1 = acc[mt][nt][hf * 2 + 1];
                if (bias) { v0 += __ldg(bias + col); v1 += __ldg(bias + col + 1); }
                if (colmask) {
                    if (__ldg(colmask + col) == 0)     v0 = NEGV;
                    if (__ldg(colmask + col + 1) == 0) v1 = NEGV;
                }
                long long o = coff + (long long)row * ldc + col;
                if (Cf) {
                    float2 w; w.x = v0; w.y = v1;
                    *(float2*)(Cf + o) = w;
                } else {
                    __half h0 = __float2half(v0);
                    __half h1 = __float2half(v1);
                    __half l0 = __float2half(v0 - __half2float(h0));
                    __half l1 = __float2half(v1 - __half2float(h1));
                    __half2 hh; hh.x = h0; hh.y = h1;
                    __half2 ll; ll.x = l0; ll.y = l1;
                    *(__half2*)(Chi + o) = hh;
                    *(__half2*)(Clo + o) = ll;
                }
            }
        }
    }
}

// ===================== softmax (writes split-fp16 P) ========================
__global__ __launch_bounds__(256)
void softmax_split_kernel(const float* __restrict__ att,
                          __half* __restrict__ Ph,
                          __half* __restrict__ Pl)
{
    __shared__ float red[256];
    __shared__ float ev[NVV];
    const int row = blockIdx.x;
    const float* a = att + (long long)row * NVV;
    const int tid = threadIdx.x;

    float mx = -INFINITY;
    for (int c = tid; c < NVV; c += 256) mx = fmaxf(mx, a[c]);
    red[tid] = mx; __syncthreads();
    for (int s = 128; s > 0; s >>= 1) {
        if (tid < s) red[tid] = fmaxf(red[tid], red[tid + s]);
        __syncthreads();
    }
    mx = red[0]; __syncthreads();

    float sum = 0.f;
    for (int c = tid; c < NVV; c += 256) {
        float e = __expf(a[c] - mx);
        ev[c] = e;
        sum += e;
    }
    red[tid] = sum; __syncthreads();
    for (int s = 128; s > 0; s >>= 1) {
        if (tid < s) red[tid] += red[tid + s];
        __syncthreads();
    }
    float inv = 1.f / red[0];
    for (int c = tid; c < NVV; c += 256) {
        float v = ev[c] * inv;
        __half h = __float2half(v);
        long long o = (long long)row * NVV + c;
        Ph[o] = h;
        Pl[o] = __float2half(v - __half2float(h));
    }
}

// ================ c[e] = sum_d kh_w[d,e] * qv_b[d]  (fp32) ==================
__global__ __launch_bounds__(256)
void c_kernel(const float* __restrict__ kh_w, const float* __restrict__ qv_b,
              float* __restrict__ c)
{
    int e = blockIdx.x * 256 + threadIdx.x;
    float acc = 0.f;
#pragma unroll 4
    for (int d = 0; d < DD; d++)
        acc = fmaf(kh_w[(long long)d * DD + e], qv_b[d], acc);
    c[e] = acc;
}

// ================= t[row] = h[row,:] . c  (per-key att bias) ================
__global__ __launch_bounds__(256)
void t_kernel(const float* __restrict__ h, const float* __restrict__ c,
              float* __restrict__ t)
{
    __shared__ float red[256];
    const int row = blockIdx.x;
    const int tid = threadIdx.x;
    const float* hr = h + (long long)row * DD;
    float4 a = *(const float4*)(hr + tid * 4);
    float4 w = *(const float4*)(c + tid * 4);
    float acc = a.x * w.x + a.y * w.y + a.z * w.z + a.w * w.w;
    red[tid] = acc; __syncthreads();
    for (int st = 128; st > 0; st >>= 1) {
        if (tid < st) red[tid] += red[tid + st];
        __syncthreads();
    }
    if (tid == 0) t[row] = red[0];
}

// ====== fused: s = sigmoid(VZ + Hv) -> z_new[:, :D]; u = s.Wu ==============
__global__ __launch_bounds__(256)
void su_kernel(const float* __restrict__ VZ, const float* __restrict__ Hv,
               const float* __restrict__ Wu,
               float* __restrict__ zout, float* __restrict__ u)
{
    __shared__ float red[256];
    const int row = blockIdx.x;
    const int tid = threadIdx.x;
    const long long base = (long long)row * DD + tid * 4;
    float4 a = *(const float4*)(VZ + base);
    float4 b = *(const float4*)(Hv + base);
    float4 w = *(const float4*)(Wu + tid * 4);
    float4 s;
    s.x = 1.f / (1.f + __expf(-(a.x + b.x)));
    s.y = 1.f / (1.f + __expf(-(a.y + b.y)));
    s.z = 1.f / (1.f + __expf(-(a.z + b.z)));
    s.w = 1.f / (1.f + __expf(-(a.w + b.w)));
    *(float4*)(zout + (long long)row * 2048 + tid * 4) = s;
    float acc = s.x * w.x + s.y * w.y + s.z * w.z + s.w * w.w;
    red[tid] = acc; __syncthreads();
    for (int st = 128; st > 0; st >>= 1) {
        if (tid < st) red[tid] += red[tid + st];
        __syncthreads();
    }
    if (tid == 0) u[row] = red[0];
}

__global__ __launch_bounds__(256)
void p_kernel(const float* __restrict__ u, const int* __restrict__ v_mask,
              float* __restrict__ p)
{
    __shared__ float red[256];
    __shared__ float vals[NVV];
    const int b = blockIdx.x;
    const int tid = threadIdx.x;

    float mx = -INFINITY;
    for (int j = tid; j < NVV; j += 256) {
        float val = (v_mask[b * NVV + j] == 0) ? NEGV : u[b * NVV + j];
        vals[j] = val;
        mx = fmaxf(mx, val);
    }
    red[tid] = mx; __syncthreads();
    for (int s = 128; s > 0; s >>= 1) {
        if (tid < s) red[tid] = fmaxf(red[tid], red[tid + s]);
        __syncthreads();
    }
    mx = red[0]; __syncthreads();

    float sum = 0.f;
    for (int j = tid; j < NVV; j += 256) {
        float e = __expf(vals[j] - mx);
        vals[j] = e;
        sum += e;
    }
    red[tid] = sum; __syncthreads();
    for (int s = 128; s > 0; s >>= 1) {
        if (tid < s) red[tid] += red[tid + s];
        __syncthreads();
    }
    float inv = 1.f / red[0];
    for (int j = tid; j < NVV; j += 256) p[b * NVV + j] = vals[j] * inv;
}

__global__ __launch_bounds__(256)
void g_kernel(const float* __restrict__ p, const float* __restrict__ v,
              float* __restrict__ g)
{
    __shared__ float ps[NVV];
    const int b = blockIdx.y;
    const int tid = threadIdx.x;
    for (int j = tid; j < NVV; j += 256) ps[j] = p[b * NVV + j];
    __syncthreads();
    const int d = blockIdx.x * 256 + tid;
    const float* vb = v + (long long)b * NVV * DD;
    float acc = 0.f;
#pragma unroll 4
    for (int j = 0; j < NVV; j++)
        acc = fmaf(ps[j], vb[(long long)j * DD + d], acc);
    g[b * DD + d] = acc;
}

__global__ __launch_bounds__(256)
void bcast_kernel(const float* __restrict__ g, float* __restrict__ hnew,
                  float* __restrict__ zout)
{
    long long i = (long long)blockIdx.x * 256 + threadIdx.x;
    int d = (int)(i & 1023);
    long long bi = i >> 10;
    int b = (int)(bi >> 10);
    float val = g[b * DD + d];
    hnew[i] = val;
    zout[bi * 2048 + DD + d] = val;
}

// ================================ launch ====================================
extern "C" void kernel_launch(void* const* d_in, const int* in_sizes, int n_in,
                              void* d_out, int out_size)
{
    const float* v      = (const float*)d_in[0];
    const float* h      = (const float*)d_in[1];
    const float* z      = (const float*)d_in[2];
    const int*   v_mask = (const int*)  d_in[3];
    const int*   h_mask = (const int*)  d_in[4];
    const float* Wv_w   = (const float*)d_in[5];
    const float* Wv_b   = (const float*)d_in[6];
    const float* Wh_w   = (const float*)d_in[7];
    const float* qv_w   = (const float*)d_in[8];
    const float* qv_b   = (const float*)d_in[9];
    const float* kh_w   = (const float*)d_in[10];
    const float* Wz_w   = (const float*)d_in[11];
    const float* Wu_w   = (const float*)d_in[12];

    float* out  = (float*)d_out;
    float* hnew = out;
    float* zout = out + (long long)MROWS * DD;

    cudaFuncSetAttribute(gemm_split, cudaFuncAttributeMaxDynamicSharedMemorySize,
                         SMEM_GEMM);

#define SYM(p, s) do { void* _t; cudaGetSymbolAddress(&_t, s); p = (decltype(p))_t; } while (0)
    __half *vzh, *vzl, *Wvzh, *hhi, *hlo, *Whh;
    __half *qvTh, *qvTl, *khTh, *WTh;
    __half *vWh, *vWl, *Ph, *Pl, *HTh;
    float *VZ, *Att, *Hv, *C, *T, *U, *P, *G;
    SYM(vzh, g_vzhi); SYM(vzl, g_vzlo);
    SYM(Wvzh, g_Wvzh);
    SYM(hhi, g_hhi); SYM(hlo, g_hlo);
    SYM(Whh, g_Whh);
    SYM(qvTh, g_qvTh); SYM(qvTl, g_qvTl);
    SYM(khTh, g_khTh);
    SYM(WTh, g_WTh);
    SYM(vWh, g_vWh); SYM(vWl, g_vWl);
    SYM(Ph, g_Ph); SYM(Pl, g_Pl); SYM(HTh, g_HTh);
    SYM(VZ, g_VZ); SYM(Att, g_att); SYM(Hv, g_Hv);
    SYM(C, g_c); SYM(T, g_t); SYM(U, g_u); SYM(P, g_p); SYM(G, g_g);
#undef SYM

    const long long PB = (long long)NVV * NVV;
    dim3 gBig(DD / BN, MROWS / BM, 1);     // (8,128,1)
    dim3 gBat(DD / BN, NVV / BM, BB);      // (8,8,16)
    dim3 gW  (DD / BN, DD / BM, 1);        // (8,8,1)

    // 1: all conversions in one launch
    megaconv<<<MC_GRID, 256>>>(v, z, Wv_w, Wz_w, h, Wh_w, qv_w, kh_w,
                               vzh, vzl, Wvzh, hhi, hlo, Whh, qvTh, qvTl, khTh);
    // 2,3: attention bias prep
    c_kernel<<<DD / 256, 256>>>(kh_w, qv_b, C);
    t_kernel<<<MROWS, 256>>>(h, C, T);

    // 4: VZ = [v|z] @ [Wv|Wz]^T + Wv_b   (K=3072)
    gemm_split<<<gBig, 256, SMEM_GEMM>>>(vzh, vzl, Wvzh, Wv_b, nullptr,
                                         VZ, nullptr, nullptr,
                                         KVZ, KVZ, KVZ, DD, 0, 0, 0, 0, 0);
    // 5: HT = (h @ Wh^T)^T  (transOut, fp16 hi only, [b, d, token])
    gemm_split<<<gBig, 256, SMEM_GEMM>>>(hhi, hlo, Whh, nullptr, nullptr,
                                         nullptr, HTh, nullptr,
                                         DD, DD, DD, DD, 1, 0, 0, 0, 0);
    // 6: W = qv_w^T @ kh_w  (transOut -> WT, hi only)
    gemm_split<<<gW, 256, SMEM_GEMM>>>(qvTh, qvTl, khTh, nullptr, nullptr,
                                       nullptr, WTh, nullptr,
                                       DD, DD, DD, DD, 1, 0, 0, 0, 0);
    // 7: vW = v @ W   (A = vz columns 0..1023 via lda=3072; split output)
    gemm_split<<<gBig, 256, SMEM_GEMM>>>(vzh, vzl, WTh, nullptr, nullptr,
                                         nullptr, vWh, vWl,
                                         DD, KVZ, DD, DD, 0, 0, 0, 0, 0);
    // 8: att[b,q,k] = vW[b,q]·h[b,k] + t[b,k]   (h_mask==0 -> NEGV)
    gemm_split<<<gBat, 256, SMEM_GEMM>>>(vWh, vWl, hhi, T, h_mask,
                                         Att, nullptr, nullptr,
                                         DD, DD, DD, NVV, 0, PB, PB, PB, NVV);
    // 9: softmax -> split-fp16 P
    softmax_split_kernel<<<MROWS, 256>>>(Att, Ph, Pl);
    // 10: Hv[b,q,d] = sum_k P[b,q,k] * HT[b,d,k]
    gemm_split<<<gBat, 256, SMEM_GEMM>>>(Ph, Pl, HTh, nullptr, nullptr,
                                         Hv, nullptr, nullptr,
                                         NVV, NVV, NVV, DD, 0, PB, PB, PB, 0);

    // ---- tail ----
    su_kernel<<<MROWS, 256>>>(VZ, Hv, Wu_w, zout, U);
    p_kernel<<<BB, 256>>>(U, v_mask, P);
    g_kernel<<<dim3(DD / 256, BB), 256>>>(P, v, G);
    bcast_kernel<<<(MROWS * DD) / 256, 256>>>(G, hnew, zout);
}

// round 16
// speedup vs baseline: 1.4188x; 1.0918x over previous
#include <cuda_runtime.h>
#include <cuda_fp16.h>
#include <cstdint>
#include <math.h>

// ---------------------------------------------------------------------------
// stack_latent_attention (B=16, NV=NH=D=1024)
// GEMMs via mma.sync.m16n8k16 fp16, fp32 accum.
// s-path GEMMs (VZ, HT, Hv): 2-term split A (hi+lo) x hi B  -> ~2.8e-4 rel.
// logit-path GEMMs (vW, att): 1-term hi x hi (softmax near-one-hot, logit
// perturbations ~0.01 abs are attenuated to ~1e-5 on Hv).
// R16: att & vW GEMMs 2->1 term (-2 term-units of MMA work).
// ---------------------------------------------------------------------------

#define BB    16
#define NVV   1024
#define DD    1024
#define MROWS (BB * NVV)
#define KVZ   (3 * DD)                 // 3072
#define NEGV  (-1e30f)

// ============================ PTX helpers ===================================
__device__ __forceinline__ uint32_t smem_u32(const void* p) {
    uint32_t a;
    asm("{ .reg .u64 t; cvta.to.shared.u64 t, %1; cvt.u32.u64 %0, t; }"
        : "=r"(a) : "l"(p));
    return a;
}

#define CP16(s, g) \
    asm volatile("cp.async.cg.shared.global [%0], [%1], 16;" \
                 :: "r"(s), "l"(g) : "memory")

#define LDSM4(r, addr) \
    asm volatile("ldmatrix.sync.aligned.m8n8.x4.shared.b16 {%0,%1,%2,%3}, [%4];" \
                 : "=r"((r)[0]), "=r"((r)[1]), "=r"((r)[2]), "=r"((r)[3]) \
                 : "r"(addr))

#define MMA(c, a, b0, b1) \
    asm volatile("mma.sync.aligned.m16n8k16.row.col.f32.f16.f16.f32 " \
                 "{%0,%1,%2,%3}, {%4,%5,%6,%7}, {%8,%9}, {%0,%1,%2,%3};" \
                 : "+f"((c)[0]), "+f"((c)[1]), "+f"((c)[2]), "+f"((c)[3]) \
                 : "r"((a)[0]), "r"((a)[1]), "r"((a)[2]), "r"((a)[3]), \
                   "r"(b0), "r"(b1))

// ============================ scratch =======================================
__device__ __align__(256) __half g_vzhi[(long long)MROWS * KVZ];
__device__ __align__(256) __half g_vzlo[(long long)MROWS * KVZ];
__device__ __align__(256) __half g_Wvzh[DD * KVZ];
__device__ __align__(256) __half g_hhi[MROWS * DD], g_hlo[MROWS * DD];
__device__ __align__(256) __half g_Whh[DD * DD];
__device__ __align__(256) __half g_qvTh[DD * DD], g_qvTl[DD * DD];
__device__ __align__(256) __half g_khTh[DD * DD];
__device__ __align__(256) __half g_WTh[DD * DD];
__device__ __align__(256) __half g_vWh[MROWS * DD];
__device__ __align__(256) __half g_Ph[MROWS * DD],  g_Pl[MROWS * DD];
__device__ __align__(256) __half g_HTh[MROWS * DD];
__device__ __align__(256) float g_VZ[MROWS * DD];
__device__ __align__(256) float g_att[(long long)BB * NVV * NVV];
__device__ __align__(256) float g_Hv[MROWS * DD];
__device__ float g_c[DD];
__device__ float g_t[MROWS];
__device__ float g_u[MROWS];
__device__ float g_p[MROWS];
__device__ float g_g[BB * DD];

// ============================ megaconv ======================================
#define MC_V   16384
#define MC_Z   (MC_V + 32768)
#define MC_WV  (MC_Z + 1024)
#define MC_WZ  (MC_WV + 2048)
#define MC_H   (MC_WZ + 16384)
#define MC_WH  (MC_H + 1024)
#define MC_QT  (MC_WH + 1024)
#define MC_KT  (MC_QT + 1024)
#define MC_GRID MC_KT

__global__ __launch_bounds__(256)
void megaconv(const float* __restrict__ v,  const float* __restrict__ z,
              const float* __restrict__ Wv, const float* __restrict__ Wz,
              const float* __restrict__ h,  const float* __restrict__ Wh,
              const float* __restrict__ qv, const float* __restrict__ kh,
              __half* __restrict__ vzh,  __half* __restrict__ vzl,
              __half* __restrict__ Wvzh,
              __half* __restrict__ hh,   __half* __restrict__ hl,
              __half* __restrict__ Whh,
              __half* __restrict__ qvTh, __half* __restrict__ qvTl,
              __half* __restrict__ khTh)
{
    __shared__ float ts[32][33];
    const int b = blockIdx.x;
    const int tid = threadIdx.x;

    if (b < MC_WH) {
        const float* src; __half *dh, *dl;
        long long i4, dst;
        if (b < MC_V) {
            i4 = (long long)b * 256 + tid;
            long long p = i4 << 2;
            src = v; dh = vzh; dl = vzl;
            dst = (p >> 10) * KVZ + (p & 1023);
        } else if (b < MC_Z) {
            i4 = (long long)(b - MC_V) * 256 + tid;
            long long p = i4 << 2;
            src = z; dh = vzh; dl = vzl;
            dst = (p >> 11) * KVZ + 1024 + (p & 2047);
        } else if (b < MC_WV) {
            i4 = (long long)(b - MC_Z) * 256 + tid;
            long long p = i4 << 2;
            src = Wv; dh = Wvzh; dl = nullptr;
            dst = (p >> 10) * KVZ + (p & 1023);
        } else if (b < MC_WZ) {
            i4 = (long long)(b - MC_WV) * 256 + tid;
            long long p = i4 << 2;
            src = Wz; dh = Wvzh; dl = nullptr;
            dst = (p >> 11) * KVZ + 1024 + (p & 2047);
        } else if (b < MC_H) {
            i4 = (long long)(b - MC_WZ) * 256 + tid;
            src = h; dh = hh; dl = hl;
            dst = i4 << 2;
        } else {
            i4 = (long long)(b - MC_H) * 256 + tid;
            src = Wh; dh = Whh; dl = nullptr;
            dst = i4 << 2;
        }
        float4 f = ((const float4*)src)[i4];
        __half hb[4], lb[4];
        float e[4] = {f.x, f.y, f.z, f.w};
#pragma unroll
        for (int k = 0; k < 4; k++) {
            hb[k] = __float2half(e[k]);
            lb[k] = __float2half(e[k] - __half2float(hb[k]));
        }
        *(uint2*)(dh + dst) = *(uint2*)hb;
        if (dl) *(uint2*)(dl + dst) = *(uint2*)lb;
    } else {
        int tb = b - MC_WH;
        const float* src; __half *dh, *dl;
        if (tb < 1024) { src = qv; dh = qvTh; dl = qvTl; }
        else           { tb -= 1024; src = kh; dh = khTh; dl = nullptr; }
        const int r0 = (tb >> 5) * 32, c0 = (tb & 31) * 32;
        const int tx = tid & 31, ty = tid >> 5;
        for (int i = ty; i < 32; i += 8)
            ts[i][tx] = src[(long long)(r0 + i) * DD + c0 + tx];
        __syncthreads();
        for (int i = ty; i < 32; i += 8) {
            float val = ts[tx][i];
            __half hbf = __float2half(val);
            long long o = (long long)(c0 + i) * DD + r0 + tx;
            dh[o] = hbf;
            if (dl) dl[o] = __float2half(val - __half2float(hbf));
        }
    }
}

// ============================ mma.sync GEMM =================================
// NT=2: C = (Ah+Al)·Bh ;  NT=1: C = Ah·Bh  (Al never loaded)
// CTA tile 128x128, BK=64, 4-stage cp.async (depth-3 prefetch), 256 threads.
// 8 warps as 2(M) x 4(N); warp tile 64x32.
// bias: per-column fp32 (+ bz*sBias).  colmask: int (+ bz*NVV), 0 -> NEGV.
// transOut=1: write C as fp16 hi (and lo if Clo) transposed [b, n, m].
#define BM    128
#define BN    128
#define BKC   64
#define PADK  72                        // row stride in fp16 elems (144 B)
#define ROWB  (PADK * 2)                // 144 bytes
#define ARR   (BM * ROWB)               // 18432 B per operand array
#define STAGE (3 * ARR)                 // Ah | Al | Bh = 55296 B
#define NSTG  4
#define SMEM_GEMM (NSTG * STAGE)        // 221184 B

template <int NT>
__global__ __launch_bounds__(256)
void gemm_split(const __half* __restrict__ Ahi, const __half* __restrict__ Alo,
                const __half* __restrict__ Bhi,
                const float* __restrict__ bias, const int* __restrict__ colmask,
                float* __restrict__ Cf,
                __half* __restrict__ Chi, __half* __restrict__ Clo,
                int K, int lda, int ldb, int ldc, int transOut,
                long long sA, long long sB, long long sC, long long sBias)
{
    extern __shared__ char smem[];
    const uint32_t sb = smem_u32(smem);
    const int tid = threadIdx.x;
    const int bz = blockIdx.z;
    Ahi += (long long)bz * sA;
    if (NT == 2) Alo += (long long)bz * sA;
    Bhi += (long long)bz * sB;
    if (bias)    bias    += (long long)bz * sBias;
    if (colmask) colmask += (long long)bz * NVV;
    const long long coff = (long long)bz * sC;
    const int m0 = blockIdx.y * BM;
    const int n0 = blockIdx.x * BN;

    const int lane = tid & 31, wid = tid >> 5;
    const int wm0 = (wid >> 2) * 64;      // 0 / 64
    const int wn0 = (wid & 3) * 32;       // 0 / 32 / 64 / 96

    float acc[4][4][4];
#pragma unroll
    for (int i = 0; i < 4; i++)
#pragma unroll
        for (int j = 0; j < 4; j++)
#pragma unroll
            for (int k = 0; k < 4; k++) acc[i][j][k] = 0.f;

    const int a_row = lane & 15;
    const int a_k   = (lane >> 4) << 3;
    const int b_row = (lane & 7) + ((lane >> 1) & 8);
    const int b_k   = ((lane >> 3) & 1) << 3;

    const int nIter = K >> 6;             // BK=64

    auto load_stage = [&](int it, int s) {
        const long long k0 = (long long)it * BKC;
        const uint32_t st = sb + s * STAGE;
#pragma unroll
        for (int j = 0; j < 4; j++) {
            int idx = tid + j * 256;            // 0..1023
            int r = idx >> 3, c = idx & 7;
            uint32_t so = r * ROWB + c * 16;
            long long ga = (long long)(m0 + r) * lda + k0 + c * 8;
            long long gb = (long long)(n0 + r) * ldb + k0 + c * 8;
            CP16(st + 0 * ARR + so, (const char*)(Ahi + ga));
            if (NT == 2) CP16(st + 1 * ARR + so, (const char*)(Alo + ga));
            CP16(st + 2 * ARR + so, (const char*)(Bhi + gb));
        }
        asm volatile("cp.async.commit_group;" ::: "memory");
    };

    load_stage(0, 0);
    if (nIter > 1) load_stage(1, 1);
    if (nIter > 2) load_stage(2, 2);

    int slot = 0;
    for (int it = 0; it < nIter; ++it) {
        asm volatile("cp.async.wait_group 2;" ::: "memory");
        __syncthreads();
        if (it + 3 < nIter) {
            int ns = slot + 3; if (ns >= NSTG) ns -= NSTG;
            load_stage(it + 3, ns);
        } else {
            asm volatile("cp.async.commit_group;" ::: "memory");
        }

        const uint32_t st = sb + slot * STAGE;
#pragma unroll
        for (int kk = 0; kk < BKC; kk += 16) {
            uint32_t ah[4][4], al[4][4], bh[2][4];
#pragma unroll
            for (int mt = 0; mt < 4; mt++) {
                uint32_t ad = st + (wm0 + 16 * mt + a_row) * ROWB + (kk + a_k) * 2;
                LDSM4(ah[mt], ad);
                if (NT == 2) LDSM4(al[mt], ad + ARR);
            }
#pragma unroll
            for (int gq = 0; gq < 2; gq++) {
                uint32_t bd = st + 2 * ARR
                            + (wn0 + gq * 16 + b_row) * ROWB + (kk + b_k) * 2;
                LDSM4(bh[gq], bd);
            }
            // term 1: Ah * Bh
#pragma unroll
            for (int mt = 0; mt < 4; mt++)
#pragma unroll
                for (int nt = 0; nt < 4; nt++)
                    MMA(acc[mt][nt], ah[mt], bh[nt >> 1][(nt & 1) * 2],
                        bh[nt >> 1][(nt & 1) * 2 + 1]);
            if (NT == 2) {
                // term 2: Al * Bh
#pragma unroll
                for (int mt = 0; mt < 4; mt++)
#pragma unroll
                    for (int nt = 0; nt < 4; nt++)
                        MMA(acc[mt][nt], al[mt], bh[nt >> 1][(nt & 1) * 2],
                            bh[nt >> 1][(nt & 1) * 2 + 1]);
            }
        }
        if (++slot == NSTG) slot = 0;
    }

    const int g2 = lane >> 2;
    const int t2 = (lane & 3) * 2;

    if (transOut) {
        __syncthreads();
        float* stage = (float*)smem;          // [BM][BN+1] = 66048 B
        const int LDS_ = BN + 1;
#pragma unroll
        for (int mt = 0; mt < 4; mt++)
#pragma unroll
            for (int hf = 0; hf < 2; hf++) {
                int row = wm0 + mt * 16 + g2 + hf * 8;
#pragma unroll
                for (int nt = 0; nt < 4; nt++) {
                    int col = wn0 + nt * 8 + t2;
                    stage[row * LDS_ + col]     = acc[mt][nt][hf * 2 + 0];
                    stage[row * LDS_ + col + 1] = acc[mt][nt][hf * 2 + 1];
                }
            }
        __syncthreads();
        const int b = m0 >> 10, tok0 = m0 & 1023;
#pragma unroll 4
        for (int i = 0; i < (BM * BN) / 256; i++) {
            int idx = i * 256 + tid;
            int m = idx & (BM - 1), n = idx >> 7;
            float val = stage[m * LDS_ + n];
            __half hbf = __float2half(val);
            long long o = ((long long)b << 20) + ((long long)(n0 + n) << 10)
                        + tok0 + m;
            Chi[o] = hbf;
            if (Clo) Clo[o] = __float2half(val - __half2float(hbf));
        }
        return;
    }

    // ---------------------------- epilogue ---------------------------------
#pragma unroll
    for (int mt = 0; mt < 4; mt++) {
#pragma unroll
        for (int hf = 0; hf < 2; hf++) {
            int row = m0 + wm0 + mt * 16 + g2 + hf * 8;
#pragma unroll
            for (int nt = 0; nt < 4; nt++) {
                int col = n0 + wn0 + nt * 8 + t2;
                float v0 = acc[mt][nt][hf * 2 + 0];
                float v1 = acc[mt][nt][hf * 2 + 1];
                if (bias) { v0 += __ldg(bias + col); v1 += __ldg(bias + col + 1); }
                if (colmask) {
                    if (__ldg(colmask + col) == 0)     v0 = NEGV;
                    if (__ldg(colmask + col + 1) == 0) v1 = NEGV;
                }
                long long o = coff + (long long)row * ldc + col;
                if (Cf) {
                    float2 w; w.x = v0; w.y = v1;
                    *(float2*)(Cf + o) = w;
                } else {
                    __half h0 = __float2half(v0);
                    __half h1 = __float2half(v1);
                    __half2 hh; hh.x = h0; hh.y = h1;
                    *(__half2*)(Chi + o) = hh;
                    if (Clo) {
                        __half2 ll;
                        ll.x = __float2half(v0 - __half2float(h0));
                        ll.y = __float2half(v1 - __half2float(h1));
                        *(__half2*)(Clo + o) = ll;
                    }
                }
            }
        }
    }
}

// ===================== softmax (writes split-fp16 P) ========================
__global__ __launch_bounds__(256)
void softmax_split_kernel(const float* __restrict__ att,
                          __half* __restrict__ Ph,
                          __half* __restrict__ Pl)
{
    __shared__ float red[256];
    __shared__ float ev[NVV];
    const int row = blockIdx.x;
    const float* a = att + (long long)row * NVV;
    const int tid = threadIdx.x;

    float mx = -INFINITY;
    for (int c = tid; c < NVV; c += 256) mx = fmaxf(mx, a[c]);
    red[tid] = mx; __syncthreads();
    for (int s = 128; s > 0; s >>= 1) {
        if (tid < s) red[tid] = fmaxf(red[tid], red[tid + s]);
        __syncthreads();
    }
    mx = red[0]; __syncthreads();

    float sum = 0.f;
    for (int c = tid; c < NVV; c += 256) {
        float e = __expf(a[c] - mx);
        ev[c] = e;
        sum += e;
    }
    red[tid] = sum; __syncthreads();
    for (int s = 128; s > 0; s >>= 1) {
        if (tid < s) red[tid] += red[tid + s];
        __syncthreads();
    }
    float inv = 1.f / red[0];
    for (int c = tid; c < NVV; c += 256) {
        float v = ev[c] * inv;
        __half h = __float2half(v);
        long long o = (long long)row * NVV + c;
        Ph[o] = h;
        Pl[o] = __float2half(v - __half2float(h));
    }
}

// ================ c[e] = sum_d kh_w[d,e] * qv_b[d]  (fp32) ==================
__global__ __launch_bounds__(256)
void c_kernel(const float* __restrict__ kh_w, const float* __restrict__ qv_b,
              float* __restrict__ c)
{
    int e = blockIdx.x * 256 + threadIdx.x;
    float acc = 0.f;
#pragma unroll 4
    for (int d = 0; d < DD; d++)
        acc = fmaf(kh_w[(long long)d * DD + e], qv_b[d], acc);
    c[e] = acc;
}

// ================= t[row] = h[row,:] . c  (per-key att bias) ================
__global__ __launch_bounds__(256)
void t_kernel(const float* __restrict__ h, const float* __restrict__ c,
              float* __restrict__ t)
{
    __shared__ float red[256];
    const int row = blockIdx.x;
    const int tid = threadIdx.x;
    const float* hr = h + (long long)row * DD;
    float4 a = *(const float4*)(hr + tid * 4);
    float4 w = *(const float4*)(c + tid * 4);
    float acc = a.x * w.x + a.y * w.y + a.z * w.z + a.w * w.w;
    red[tid] = acc; __syncthreads();
    for (int st = 128; st > 0; st >>= 1) {
        if (tid < st) red[tid] += red[tid + st];
        __syncthreads();
    }
    if (tid == 0) t[row] = red[0];
}

// ====== fused: s = sigmoid(VZ + Hv) -> z_new[:, :D]; u = s.Wu ==============
__global__ __launch_bounds__(256)
void su_kernel(const float* __restrict__ VZ, const float* __restrict__ Hv,
               const float* __restrict__ Wu,
               float* __restrict__ zout, float* __restrict__ u)
{
    __shared__ float red[256];
    const int row = blockIdx.x;
    const int tid = threadIdx.x;
    const long long base = (long long)row * DD + tid * 4;
    float4 a = *(const float4*)(VZ + base);
    float4 b = *(const float4*)(Hv + base);
    float4 w = *(const float4*)(Wu + tid * 4);
    float4 s;
    s.x = 1.f / (1.f + __expf(-(a.x + b.x)));
    s.y = 1.f / (1.f + __expf(-(a.y + b.y)));
    s.z = 1.f / (1.f + __expf(-(a.z + b.z)));
    s.w = 1.f / (1.f + __expf(-(a.w + b.w)));
    *(float4*)(zout + (long long)row * 2048 + tid * 4) = s;
    float acc = s.x * w.x + s.y * w.y + s.z * w.z + s.w * w.w;
    red[tid] = acc; __syncthreads();
    for (int st = 128; st > 0; st >>= 1) {
        if (tid < st) red[tid] += red[tid + st];
        __syncthreads();
    }
    if (tid == 0) u[row] = red[0];
}

__global__ __launch_bounds__(256)
void p_kernel(const float* __restrict__ u, const int* __restrict__ v_mask,
              float* __restrict__ p)
{
    __shared__ float red[256];
    __shared__ float vals[NVV];
    const int b = blockIdx.x;
    const int tid = threadIdx.x;

    float mx = -INFINITY;
    for (int j = tid; j < NVV; j += 256) {
        float val = (v_mask[b * NVV + j] == 0) ? NEGV : u[b * NVV + j];
        vals[j] = val;
        mx = fmaxf(mx, val);
    }
    red[tid] = mx; __syncthreads();
    for (int s = 128; s > 0; s >>= 1) {
        if (tid < s) red[tid] = fmaxf(red[tid], red[tid + s]);
        __syncthreads();
    }
    mx = red[0]; __syncthreads();

    float sum = 0.f;
    for (int j = tid; j < NVV; j += 256) {
        float e = __expf(vals[j] - mx);
        vals[j] = e;
        sum += e;
    }
    red[tid] = sum; __syncthreads();
    for (int s = 128; s > 0; s >>= 1) {
        if (tid < s) red[tid] += red[tid + s];
        __syncthreads();
    }
    float inv = 1.f / red[0];
    for (int j = tid; j < NVV; j += 256) p[b * NVV + j] = vals[j] * inv;
}

__global__ __launch_bounds__(256)
void g_kernel(const float* __restrict__ p, const float* __restrict__ v,
              float* __restrict__ g)
{
    __shared__ float ps[NVV];
    const int b = blockIdx.y;
    const int tid = threadIdx.x;
    for (int j = tid; j < NVV; j += 256) ps[j] = p[b * NVV + j];
    __syncthreads();
    const int d = blockIdx.x * 256 + tid;
    const float* vb = v + (long long)b * NVV * DD;
    float acc = 0.f;
#pragma unroll 4
    for (int j = 0; j < NVV; j++)
        acc = fmaf(ps[j], vb[(long long)j * DD + d], acc);
    g[b * DD + d] = acc;
}

__global__ __launch_bounds__(256)
void bcast_kernel(const float* __restrict__ g, float* __restrict__ hnew,
                  float* __restrict__ zout)
{
    long long i = (long long)blockIdx.x * 256 + threadIdx.x;
    int d = (int)(i & 1023);
    long long bi = i >> 10;
    int b = (int)(bi >> 10);
    float val = g[b * DD + d];
    hnew[i] = val;
    zout[bi * 2048 + DD + d] = val;
}

// ================================ launch ====================================
extern "C" void kernel_launch(void* const* d_in, const int* in_sizes, int n_in,
                              void* d_out, int out_size)
{
    const float* v      = (const float*)d_in[0];
    const float* h      = (const float*)d_in[1];
    const float* z      = (const float*)d_in[2];
    const int*   v_mask = (const int*)  d_in[3];
    const int*   h_mask = (const int*)  d_in[4];
    const float* Wv_w   = (const float*)d_in[5];
    const float* Wv_b   = (const float*)d_in[6];
    const float* Wh_w   = (const float*)d_in[7];
    const float* qv_w   = (const float*)d_in[8];
    const float* qv_b   = (const float*)d_in[9];
    const float* kh_w   = (const float*)d_in[10];
    const float* Wz_w   = (const float*)d_in[11];
    const float* Wu_w   = (const float*)d_in[12];

    float* out  = (float*)d_out;
    float* hnew = out;
    float* zout = out + (long long)MROWS * DD;

    cudaFuncSetAttribute(gemm_split<2>, cudaFuncAttributeMaxDynamicSharedMemorySize,
                         SMEM_GEMM);
    cudaFuncSetAttribute(gemm_split<1>, cudaFuncAttributeMaxDynamicSharedMemorySize,
                         SMEM_GEMM);

#define SYM(p, s) do { void* _t; cudaGetSymbolAddress(&_t, s); p = (decltype(p))_t; } while (0)
    __half *vzh, *vzl, *Wvzh, *hhi, *hlo, *Whh;
    __half *qvTh, *qvTl, *khTh, *WTh;
    __half *vWh, *Ph, *Pl, *HTh;
    float *VZ, *Att, *Hv, *C, *T, *U, *P, *G;
    SYM(vzh, g_vzhi); SYM(vzl, g_vzlo);
    SYM(Wvzh, g_Wvzh);
    SYM(hhi, g_hhi); SYM(hlo, g_hlo);
    SYM(Whh, g_Whh);
    SYM(qvTh, g_qvTh); SYM(qvTl, g_qvTl);
    SYM(khTh, g_khTh);
    SYM(WTh, g_WTh);
    SYM(vWh, g_vWh);
    SYM(Ph, g_Ph); SYM(Pl, g_Pl); SYM(HTh, g_HTh);
    SYM(VZ, g_VZ); SYM(Att, g_att); SYM(Hv, g_Hv);
    SYM(C, g_c); SYM(T, g_t); SYM(U, g_u); SYM(P, g_p); SYM(G, g_g);
#undef SYM

    const long long PB = (long long)NVV * NVV;
    dim3 gBig(DD / BN, MROWS / BM, 1);     // (8,128,1)
    dim3 gBat(DD / BN, NVV / BM, BB);      // (8,8,16)
    dim3 gW  (DD / BN, DD / BM, 1);        // (8,8,1)

    // 1: all conversions in one launch
    megaconv<<<MC_GRID, 256>>>(v, z, Wv_w, Wz_w, h, Wh_w, qv_w, kh_w,
                               vzh, vzl, Wvzh, hhi, hlo, Whh, qvTh, qvTl, khTh);
    // 2,3: attention bias prep
    c_kernel<<<DD / 256, 256>>>(kh_w, qv_b, C);
    t_kernel<<<MROWS, 256>>>(h, C, T);

    // 4: VZ = [v|z] @ [Wv|Wz]^T + Wv_b   (K=3072, 2-term: s-path)
    gemm_split<2><<<gBig, 256, SMEM_GEMM>>>(vzh, vzl, Wvzh, Wv_b, nullptr,
                                            VZ, nullptr, nullptr,
                                            KVZ, KVZ, KVZ, DD, 0, 0, 0, 0, 0);
    // 5: HT = (h @ Wh^T)^T  (transOut, hi only; 2-term: s-path)
    gemm_split<2><<<gBig, 256, SMEM_GEMM>>>(hhi, hlo, Whh, nullptr, nullptr,
                                            nullptr, HTh, nullptr,
                                            DD, DD, DD, DD, 1, 0, 0, 0, 0);
    // 6: W = qv_w^T @ kh_w  (transOut -> WT, hi only; 2-term, tiny)
    gemm_split<2><<<gW, 256, SMEM_GEMM>>>(qvTh, qvTl, khTh, nullptr, nullptr,
                                          nullptr, WTh, nullptr,
                                          DD, DD, DD, DD, 1, 0, 0, 0, 0);
    // 7: vW = v @ W  (1-term: logit path; hi output only)
    gemm_split<1><<<gBig, 256, SMEM_GEMM>>>(vzh, nullptr, WTh, nullptr, nullptr,
                                            nullptr, vWh, nullptr,
                                            DD, KVZ, DD, DD, 0, 0, 0, 0, 0);
    // 8: att = vW·h + t[k]  (1-term: logit path; h_mask==0 -> NEGV)
    gemm_split<1><<<gBat, 256, SMEM_GEMM>>>(vWh, nullptr, hhi, T, h_mask,
                                            Att, nullptr, nullptr,
                                            DD, DD, DD, NVV, 0, PB, PB, PB, NVV);
    // 9: softmax -> split-fp16 P
    softmax_split_kernel<<<MROWS, 256>>>(Att, Ph, Pl);
    // 10: Hv = P @ HT^T  (2-term: s-path)
    gemm_split<2><<<gBat, 256, SMEM_GEMM>>>(Ph, Pl, HTh, nullptr, nullptr,
                                            Hv, nullptr, nullptr,
                                            NVV, NVV, NVV, DD, 0, PB, PB, PB, 0);

    // ---- tail ----
    su_kernel<<<MROWS, 256>>>(VZ, Hv, Wu_w, zout, U);
    p_kernel<<<BB, 256>>>(U, v_mask, P);
    g_kernel<<<dim3(DD / 256, BB), 256>>>(P, v, G);
    bcast_kernel<<<(MROWS * DD) / 256, 256>>>(G, hnew, zout);
}

// round 17
// speedup vs baseline: 1.5405x; 1.0857x over previous
#include <cuda_runtime.h>
#include <cuda_fp16.h>
#include <cstdint>
#include <math.h>

// ---------------------------------------------------------------------------
// stack_latent_attention (B=16, NV=NH=D=1024)
// GEMMs via mma.sync.m16n8k16 fp16, fp32 accum.
// s-path GEMMs (VZ, HT, Hv): 2-term split A (hi+lo) x hi B.
// logit-path GEMMs (vW, att): 1-term hi x hi.
// R17: 2-stage pipeline + 2 CTAs/SM (independent barrier domains -> pipeline
//      phases can interleave anti-phase, filling the 40% tensor-idle windows
//      that persisted across all single-CTA configs).
// ---------------------------------------------------------------------------

#define BB    16
#define NVV   1024
#define DD    1024
#define MROWS (BB * NVV)
#define KVZ   (3 * DD)                 // 3072
#define NEGV  (-1e30f)

// ============================ PTX helpers ===================================
__device__ __forceinline__ uint32_t smem_u32(const void* p) {
    uint32_t a;
    asm("{ .reg .u64 t; cvta.to.shared.u64 t, %1; cvt.u32.u64 %0, t; }"
        : "=r"(a) : "l"(p));
    return a;
}

#define CP16(s, g) \
    asm volatile("cp.async.cg.shared.global [%0], [%1], 16;" \
                 :: "r"(s), "l"(g) : "memory")

#define LDSM4(r, addr) \
    asm volatile("ldmatrix.sync.aligned.m8n8.x4.shared.b16 {%0,%1,%2,%3}, [%4];" \
                 : "=r"((r)[0]), "=r"((r)[1]), "=r"((r)[2]), "=r"((r)[3]) \
                 : "r"(addr))

#define MMA(c, a, b0, b1) \
    asm volatile("mma.sync.aligned.m16n8k16.row.col.f32.f16.f16.f32 " \
                 "{%0,%1,%2,%3}, {%4,%5,%6,%7}, {%8,%9}, {%0,%1,%2,%3};" \
                 : "+f"((c)[0]), "+f"((c)[1]), "+f"((c)[2]), "+f"((c)[3]) \
                 : "r"((a)[0]), "r"((a)[1]), "r"((a)[2]), "r"((a)[3]), \
                   "r"(b0), "r"(b1))

// ============================ scratch =======================================
__device__ __align__(256) __half g_vzhi[(long long)MROWS * KVZ];
__device__ __align__(256) __half g_vzlo[(long long)MROWS * KVZ];
__device__ __align__(256) __half g_Wvzh[DD * KVZ];
__device__ __align__(256) __half g_hhi[MROWS * DD], g_hlo[MROWS * DD];
__device__ __align__(256) __half g_Whh[DD * DD];
__device__ __align__(256) __half g_qvTh[DD * DD], g_qvTl[DD * DD];
__device__ __align__(256) __half g_khTh[DD * DD];
__device__ __align__(256) __half g_WTh[DD * DD];
__device__ __align__(256) __half g_vWh[MROWS * DD];
__device__ __align__(256) __half g_Ph[MROWS * DD],  g_Pl[MROWS * DD];
__device__ __align__(256) __half g_HTh[MROWS * DD];
__device__ __align__(256) float g_VZ[MROWS * DD];
__device__ __align__(256) float g_att[(long long)BB * NVV * NVV];
__device__ __align__(256) float g_Hv[MROWS * DD];
__device__ float g_c[DD];
__device__ float g_t[MROWS];
__device__ float g_u[MROWS];
__device__ float g_p[MROWS];
__device__ float g_g[BB * DD];

// ============================ megaconv ======================================
#define MC_V   16384
#define MC_Z   (MC_V + 32768)
#define MC_WV  (MC_Z + 1024)
#define MC_WZ  (MC_WV + 2048)
#define MC_H   (MC_WZ + 16384)
#define MC_WH  (MC_H + 1024)
#define MC_QT  (MC_WH + 1024)
#define MC_KT  (MC_QT + 1024)
#define MC_GRID MC_KT

__global__ __launch_bounds__(256)
void megaconv(const float* __restrict__ v,  const float* __restrict__ z,
              const float* __restrict__ Wv, const float* __restrict__ Wz,
              const float* __restrict__ h,  const float* __restrict__ Wh,
              const float* __restrict__ qv, const float* __restrict__ kh,
              __half* __restrict__ vzh,  __half* __restrict__ vzl,
              __half* __restrict__ Wvzh,
              __half* __restrict__ hh,   __half* __restrict__ hl,
              __half* __restrict__ Whh,
              __half* __restrict__ qvTh, __half* __restrict__ qvTl,
              __half* __restrict__ khTh)
{
    __shared__ float ts[32][33];
    const int b = blockIdx.x;
    const int tid = threadIdx.x;

    if (b < MC_WH) {
        const float* src; __half *dh, *dl;
        long long i4, dst;
        if (b < MC_V) {
            i4 = (long long)b * 256 + tid;
            long long p = i4 << 2;
            src = v; dh = vzh; dl = vzl;
            dst = (p >> 10) * KVZ + (p & 1023);
        } else if (b < MC_Z) {
            i4 = (long long)(b - MC_V) * 256 + tid;
            long long p = i4 << 2;
            src = z; dh = vzh; dl = vzl;
            dst = (p >> 11) * KVZ + 1024 + (p & 2047);
        } else if (b < MC_WV) {
            i4 = (long long)(b - MC_Z) * 256 + tid;
            long long p = i4 << 2;
            src = Wv; dh = Wvzh; dl = nullptr;
            dst = (p >> 10) * KVZ + (p & 1023);
        } else if (b < MC_WZ) {
            i4 = (long long)(b - MC_WV) * 256 + tid;
            long long p = i4 << 2;
            src = Wz; dh = Wvzh; dl = nullptr;
            dst = (p >> 11) * KVZ + 1024 + (p & 2047);
        } else if (b < MC_H) {
            i4 = (long long)(b - MC_WZ) * 256 + tid;
            src = h; dh = hh; dl = hl;
            dst = i4 << 2;
        } else {
            i4 = (long long)(b - MC_H) * 256 + tid;
            src = Wh; dh = Whh; dl = nullptr;
            dst = i4 << 2;
        }
        float4 f = ((const float4*)src)[i4];
        __half hb[4], lb[4];
        float e[4] = {f.x, f.y, f.z, f.w};
#pragma unroll
        for (int k = 0; k < 4; k++) {
            hb[k] = __float2half(e[k]);
            lb[k] = __float2half(e[k] - __half2float(hb[k]));
        }
        *(uint2*)(dh + dst) = *(uint2*)hb;
        if (dl) *(uint2*)(dl + dst) = *(uint2*)lb;
    } else {
        int tb = b - MC_WH;
        const float* src; __half *dh, *dl;
        if (tb < 1024) { src = qv; dh = qvTh; dl = qvTl; }
        else           { tb -= 1024; src = kh; dh = khTh; dl = nullptr; }
        const int r0 = (tb >> 5) * 32, c0 = (tb & 31) * 32;
        const int tx = tid & 31, ty = tid >> 5;
        for (int i = ty; i < 32; i += 8)
            ts[i][tx] = src[(long long)(r0 + i) * DD + c0 + tx];
        __syncthreads();
        for (int i = ty; i < 32; i += 8) {
            float val = ts[tx][i];
            __half hbf = __float2half(val);
            long long o = (long long)(c0 + i) * DD + r0 + tx;
            dh[o] = hbf;
            if (dl) dl[o] = __float2half(val - __half2float(hbf));
        }
    }
}

// ============================ mma.sync GEMM =================================
// NT=2: C = (Ah+Al)·Bh ;  NT=1: C = Ah·Bh  (Al never loaded)
// CTA tile 128x128, BK=64, 2-stage cp.async, 256 threads, 2 CTAs/SM.
// 8 warps as 2(M) x 4(N); warp tile 64x32.
// bias: per-column fp32 (+ bz*sBias).  colmask: int (+ bz*NVV), 0 -> NEGV.
// transOut=1: write C as fp16 hi (and lo if Clo) transposed [b, n, m].
#define BM    128
#define BN    128
#define BKC   64
#define PADK  72                        // row stride in fp16 elems (144 B)
#define ROWB  (PADK * 2)                // 144 bytes
#define ARR   (BM * ROWB)               // 18432 B per operand array
#define STAGE (3 * ARR)                 // Ah | Al | Bh = 55296 B
#define NSTG  2
#define SMEM_GEMM (NSTG * STAGE)        // 110592 B -> 2 CTAs/SM

template <int NT>
__global__ __launch_bounds__(256, 2)
void gemm_split(const __half* __restrict__ Ahi, const __half* __restrict__ Alo,
                const __half* __restrict__ Bhi,
                const float* __restrict__ bias, const int* __restrict__ colmask,
                float* __restrict__ Cf,
                __half* __restrict__ Chi, __half* __restrict__ Clo,
                int K, int lda, int ldb, int ldc, int transOut,
                long long sA, long long sB, long long sC, long long sBias)
{
    extern __shared__ char smem[];
    const uint32_t sb = smem_u32(smem);
    const int tid = threadIdx.x;
    const int bz = blockIdx.z;
    Ahi += (long long)bz * sA;
    if (NT == 2) Alo += (long long)bz * sA;
    Bhi += (long long)bz * sB;
    if (bias)    bias    += (long long)bz * sBias;
    if (colmask) colmask += (long long)bz * NVV;
    const long long coff = (long long)bz * sC;
    const int m0 = blockIdx.y * BM;
    const int n0 = blockIdx.x * BN;

    const int lane = tid & 31, wid = tid >> 5;
    const int wm0 = (wid >> 2) * 64;      // 0 / 64
    const int wn0 = (wid & 3) * 32;       // 0 / 32 / 64 / 96

    float acc[4][4][4];
#pragma unroll
    for (int i = 0; i < 4; i++)
#pragma unroll
        for (int j = 0; j < 4; j++)
#pragma unroll
            for (int k = 0; k < 4; k++) acc[i][j][k] = 0.f;

    const int a_row = lane & 15;
    const int a_k   = (lane >> 4) << 3;
    const int b_row = (lane & 7) + ((lane >> 1) & 8);
    const int b_k   = ((lane >> 3) & 1) << 3;

    const int nIter = K >> 6;             // BK=64

    auto load_stage = [&](int it, int s) {
        const long long k0 = (long long)it * BKC;
        const uint32_t st = sb + s * STAGE;
#pragma unroll
        for (int j = 0; j < 4; j++) {
            int idx = tid + j * 256;            // 0..1023
            int r = idx >> 3, c = idx & 7;
            uint32_t so = r * ROWB + c * 16;
            long long ga = (long long)(m0 + r) * lda + k0 + c * 8;
            long long gb = (long long)(n0 + r) * ldb + k0 + c * 8;
            CP16(st + 0 * ARR + so, (const char*)(Ahi + ga));
            if (NT == 2) CP16(st + 1 * ARR + so, (const char*)(Alo + ga));
            CP16(st + 2 * ARR + so, (const char*)(Bhi + gb));
        }
        asm volatile("cp.async.commit_group;" ::: "memory");
    };

    load_stage(0, 0);

    for (int it = 0; it < nIter; ++it) {
        asm volatile("cp.async.wait_group 0;" ::: "memory");
        __syncthreads();
        // All warps finished reading stage it-1 (slot (it+1)&1) before this
        // barrier, so prefetching it+1 into that slot is safe.
        if (it + 1 < nIter) load_stage(it + 1, (it + 1) & 1);

        const uint32_t st = sb + (it & 1) * STAGE;
#pragma unroll
        for (int kk = 0; kk < BKC; kk += 16) {
            uint32_t ah[4][4], al[4][4], bh[2][4];
#pragma unroll
            for (int mt = 0; mt < 4; mt++) {
                uint32_t ad = st + (wm0 + 16 * mt + a_row) * ROWB + (kk + a_k) * 2;
                LDSM4(ah[mt], ad);
                if (NT == 2) LDSM4(al[mt], ad + ARR);
            }
#pragma unroll
            for (int gq = 0; gq < 2; gq++) {
                uint32_t bd = st + 2 * ARR
                            + (wn0 + gq * 16 + b_row) * ROWB + (kk + b_k) * 2;
                LDSM4(bh[gq], bd);
            }
            // term 1: Ah * Bh
#pragma unroll
            for (int mt = 0; mt < 4; mt++)
#pragma unroll
                for (int nt = 0; nt < 4; nt++)
                    MMA(acc[mt][nt], ah[mt], bh[nt >> 1][(nt & 1) * 2],
                        bh[nt >> 1][(nt & 1) * 2 + 1]);
            if (NT == 2) {
                // term 2: Al * Bh
#pragma unroll
                for (int mt = 0; mt < 4; mt++)
#pragma unroll
                    for (int nt = 0; nt < 4; nt++)
                        MMA(acc[mt][nt], al[mt], bh[nt >> 1][(nt & 1) * 2],
                            bh[nt >> 1][(nt & 1) * 2 + 1]);
            }
        }
        __syncthreads();
    }

    const int g2 = lane >> 2;
    const int t2 = (lane & 3) * 2;

    if (transOut) {
        float* stage = (float*)smem;          // [BM][BN+1] = 66048 B
        const int LDS_ = BN + 1;
#pragma unroll
        for (int mt = 0; mt < 4; mt++)
#pragma unroll
            for (int hf = 0; hf < 2; hf++) {
                int row = wm0 + mt * 16 + g2 + hf * 8;
#pragma unroll
                for (int nt = 0; nt < 4; nt++) {
                    int col = wn0 + nt * 8 + t2;
                    stage[row * LDS_ + col]     = acc[mt][nt][hf * 2 + 0];
                    stage[row * LDS_ + col + 1] = acc[mt][nt][hf * 2 + 1];
                }
            }
        __syncthreads();
        const int b = m0 >> 10, tok0 = m0 & 1023;
#pragma unroll 4
        for (int i = 0; i < (BM * BN) / 256; i++) {
            int idx = i * 256 + tid;
            int m = idx & (BM - 1), n = idx >> 7;
            float val = stage[m * LDS_ + n];
            __half hbf = __float2half(val);
            long long o = ((long long)b << 20) + ((long long)(n0 + n) << 10)
                        + tok0 + m;
            Chi[o] = hbf;
            if (Clo) Clo[o] = __float2half(val - __half2float(hbf));
        }
        return;
    }

    // ---------------------------- epilogue ---------------------------------
#pragma unroll
    for (int mt = 0; mt < 4; mt++) {
#pragma unroll
        for (int hf = 0; hf < 2; hf++) {
            int row = m0 + wm0 + mt * 16 + g2 + hf * 8;
#pragma unroll
            for (int nt = 0; nt < 4; nt++) {
                int col = n0 + wn0 + nt * 8 + t2;
                float v0 = acc[mt][nt][hf * 2 + 0];
                float v1 = acc[mt][nt][hf * 2 + 1];
                if (bias) { v0 += __ldg(bias + col); v1 += __ldg(bias + col + 1); }
                if (colmask) {
                    if (__ldg(colmask + col) == 0)     v0 = NEGV;
                    if (__ldg(colmask + col + 1) == 0) v1 = NEGV;
                }
                long long o = coff + (long long)row * ldc + col;
                if (Cf) {
                    float2 w; w.x = v0; w.y = v1;
                    *(float2*)(Cf + o) = w;
                } else {
                    __half h0 = __float2half(v0);
                    __half h1 = __float2half(v1);
                    __half2 hh; hh.x = h0; hh.y = h1;
                    *(__half2*)(Chi + o) = hh;
                    if (Clo) {
                        __half2 ll;
                        ll.x = __float2half(v0 - __half2float(h0));
                        ll.y = __float2half(v1 - __half2float(h1));
                        *(__half2*)(Clo + o) = ll;
                    }
                }
            }
        }
    }
}

// ===================== softmax (writes split-fp16 P) ========================
__global__ __launch_bounds__(256)
void softmax_split_kernel(const float* __restrict__ att,
                          __half* __restrict__ Ph,
                          __half* __restrict__ Pl)
{
    __shared__ float red[256];
    __shared__ float ev[NVV];
    const int row = blockIdx.x;
    const float* a = att + (long long)row * NVV;
    const int tid = threadIdx.x;

    float mx = -INFINITY;
    for (int c = tid; c < NVV; c += 256) mx = fmaxf(mx, a[c]);
    red[tid] = mx; __syncthreads();
    for (int s = 128; s > 0; s >>= 1) {
        if (tid < s) red[tid] = fmaxf(red[tid], red[tid + s]);
        __syncthreads();
    }
    mx = red[0]; __syncthreads();

    float sum = 0.f;
    for (int c = tid; c < NVV; c += 256) {
        float e = __expf(a[c] - mx);
        ev[c] = e;
        sum += e;
    }
    red[tid] = sum; __syncthreads();
    for (int s = 128; s > 0; s >>= 1) {
        if (tid < s) red[tid] += red[tid + s];
        __syncthreads();
    }
    float inv = 1.f / red[0];
    for (int c = tid; c < NVV; c += 256) {
        float v = ev[c] * inv;
        __half h = __float2half(v);
        long long o = (long long)row * NVV + c;
        Ph[o] = h;
        Pl[o] = __float2half(v - __half2float(h));
    }
}

// ================ c[e] = sum_d kh_w[d,e] * qv_b[d]  (fp32) ==================
__global__ __launch_bounds__(256)
void c_kernel(const float* __restrict__ kh_w, const float* __restrict__ qv_b,
              float* __restrict__ c)
{
    int e = blockIdx.x * 256 + threadIdx.x;
    float acc = 0.f;
#pragma unroll 4
    for (int d = 0; d < DD; d++)
        acc = fmaf(kh_w[(long long)d * DD + e], qv_b[d], acc);
    c[e] = acc;
}

// ================= t[row] = h[row,:] . c  (per-key att bias) ================
__global__ __launch_bounds__(256)
void t_kernel(const float* __restrict__ h, const float* __restrict__ c,
              float* __restrict__ t)
{
    __shared__ float red[256];
    const int row = blockIdx.x;
    const int tid = threadIdx.x;
    const float* hr = h + (long long)row * DD;
    float4 a = *(const float4*)(hr + tid * 4);
    float4 w = *(const float4*)(c + tid * 4);
    float acc = a.x * w.x + a.y * w.y + a.z * w.z + a.w * w.w;
    red[tid] = acc; __syncthreads();
    for (int st = 128; st > 0; st >>= 1) {
        if (tid < st) red[tid] += red[tid + st];
        __syncthreads();
    }
    if (tid == 0) t[row] = red[0];
}

// ====== fused: s = sigmoid(VZ + Hv) -> z_new[:, :D]; u = s.Wu ==============
__global__ __launch_bounds__(256)
void su_kernel(const float* __restrict__ VZ, const float* __restrict__ Hv,
               const float* __restrict__ Wu,
               float* __restrict__ zout, float* __restrict__ u)
{
    __shared__ float red[256];
    const int row = blockIdx.x;
    const int tid = threadIdx.x;
    const long long base = (long long)row * DD + tid * 4;
    float4 a = *(const float4*)(VZ + base);
    float4 b = *(const float4*)(Hv + base);
    float4 w = *(const float4*)(Wu + tid * 4);
    float4 s;
    s.x = 1.f / (1.f + __expf(-(a.x + b.x)));
    s.y = 1.f / (1.f + __expf(-(a.y + b.y)));
    s.z = 1.f / (1.f + __expf(-(a.z + b.z)));
    s.w = 1.f / (1.f + __expf(-(a.w + b.w)));
    *(float4*)(zout + (long long)row * 2048 + tid * 4) = s;
    float acc = s.x * w.x + s.y * w.y + s.z * w.z + s.w * w.w;
    red[tid] = acc; __syncthreads();
    for (int st = 128; st > 0; st >>= 1) {
        if (tid < st) red[tid] += red[tid + st];
        __syncthreads();
    }
    if (tid == 0) u[row] = red[0];
}

__global__ __launch_bounds__(256)
void p_kernel(const float* __restrict__ u, const int* __restrict__ v_mask,
              float* __restrict__ p)
{
    __shared__ float red[256];
    __shared__ float vals[NVV];
    const int b = blockIdx.x;
    const int tid = threadIdx.x;

    float mx = -INFINITY;
    for (int j = tid; j < NVV; j += 256) {
        float val = (v_mask[b * NVV + j] == 0) ? NEGV : u[b * NVV + j];
        vals[j] = val;
        mx = fmaxf(mx, val);
    }
    red[tid] = mx; __syncthreads();
    for (int s = 128; s > 0; s >>= 1) {
        if (tid < s) red[tid] = fmaxf(red[tid], red[tid + s]);
        __syncthreads();
    }
    mx = red[0]; __syncthreads();

    float sum = 0.f;
    for (int j = tid; j < NVV; j += 256) {
        float e = __expf(vals[j] - mx);
        vals[j] = e;
        sum += e;
    }
    red[tid] = sum; __syncthreads();
    for (int s = 128; s > 0; s >>= 1) {
        if (tid < s) red[tid] += red[tid + s];
        __syncthreads();
    }
    float inv = 1.f / red[0];
    for (int j = tid; j < NVV; j += 256) p[b * NVV + j] = vals[j] * inv;
}

__global__ __launch_bounds__(256)
void g_kernel(const float* __restrict__ p, const float* __restrict__ v,
              float* __restrict__ g)
{
    __shared__ float ps[NVV];
    const int b = blockIdx.y;
    const int tid = threadIdx.x;
    for (int j = tid; j < NVV; j += 256) ps[j] = p[b * NVV + j];
    __syncthreads();
    const int d = blockIdx.x * 256 + tid;
    const float* vb = v + (long long)b * NVV * DD;
    float acc = 0.f;
#pragma unroll 4
    for (int j = 0; j < NVV; j++)
        acc = fmaf(ps[j], vb[(long long)j * DD + d], acc);
    g[b * DD + d] = acc;
}

__global__ __launch_bounds__(256)
void bcast_kernel(const float* __restrict__ g, float* __restrict__ hnew,
                  float* __restrict__ zout)
{
    long long i = (long long)blockIdx.x * 256 + threadIdx.x;
    int d = (int)(i & 1023);
    long long bi = i >> 10;
    int b = (int)(bi >> 10);
    float val = g[b * DD + d];
    hnew[i] = val;
    zout[bi * 2048 + DD + d] = val;
}

// ================================ launch ====================================
extern "C" void kernel_launch(void* const* d_in, const int* in_sizes, int n_in,
                              void* d_out, int out_size)
{
    const float* v      = (const float*)d_in[0];
    const float* h      = (const float*)d_in[1];
    const float* z      = (const float*)d_in[2];
    const int*   v_mask = (const int*)  d_in[3];
    const int*   h_mask = (const int*)  d_in[4];
    const float* Wv_w   = (const float*)d_in[5];
    const float* Wv_b   = (const float*)d_in[6];
    const float* Wh_w   = (const float*)d_in[7];
    const float* qv_w   = (const float*)d_in[8];
    const float* qv_b   = (const float*)d_in[9];
    const float* kh_w   = (const float*)d_in[10];
    const float* Wz_w   = (const float*)d_in[11];
    const float* Wu_w   = (const float*)d_in[12];

    float* out  = (float*)d_out;
    float* hnew = out;
    float* zout = out + (long long)MROWS * DD;

    cudaFuncSetAttribute(gemm_split<2>, cudaFuncAttributeMaxDynamicSharedMemorySize,
                         SMEM_GEMM);
    cudaFuncSetAttribute(gemm_split<1>, cudaFuncAttributeMaxDynamicSharedMemorySize,
                         SMEM_GEMM);

#define SYM(p, s) do { void* _t; cudaGetSymbolAddress(&_t, s); p = (decltype(p))_t; } while (0)
    __half *vzh, *vzl, *Wvzh, *hhi, *hlo, *Whh;
    __half *qvTh, *qvTl, *khTh, *WTh;
    __half *vWh, *Ph, *Pl, *HTh;
    float *VZ, *Att, *Hv, *C, *T, *U, *P, *G;
    SYM(vzh, g_vzhi); SYM(vzl, g_vzlo);
    SYM(Wvzh, g_Wvzh);
    SYM(hhi, g_hhi); SYM(hlo, g_hlo);
    SYM(Whh, g_Whh);
    SYM(qvTh, g_qvTh); SYM(qvTl, g_qvTl);
    SYM(khTh, g_khTh);
    SYM(WTh, g_WTh);
    SYM(vWh, g_vWh);
    SYM(Ph, g_Ph); SYM(Pl, g_Pl); SYM(HTh, g_HTh);
    SYM(VZ, g_VZ); SYM(Att, g_att); SYM(Hv, g_Hv);
    SYM(C, g_c); SYM(T, g_t); SYM(U, g_u); SYM(P, g_p); SYM(G, g_g);
#undef SYM

    const long long PB = (long long)NVV * NVV;
    dim3 gBig(DD / BN, MROWS / BM, 1);     // (8,128,1)
    dim3 gBat(DD / BN, NVV / BM, BB);      // (8,8,16)
    dim3 gW  (DD / BN, DD / BM, 1);        // (8,8,1)

    // 1: all conversions in one launch
    megaconv<<<MC_GRID, 256>>>(v, z, Wv_w, Wz_w, h, Wh_w, qv_w, kh_w,
                               vzh, vzl, Wvzh, hhi, hlo, Whh, qvTh, qvTl, khTh);
    // 2,3: attention bias prep
    c_kernel<<<DD / 256, 256>>>(kh_w, qv_b, C);
    t_kernel<<<MROWS, 256>>>(h, C, T);

    // 4: VZ = [v|z] @ [Wv|Wz]^T + Wv_b   (K=3072, 2-term: s-path)
    gemm_split<2><<<gBig, 256, SMEM_GEMM>>>(vzh, vzl, Wvzh, Wv_b, nullptr,
                                            VZ, nullptr, nullptr,
                                            KVZ, KVZ, KVZ, DD, 0, 0, 0, 0, 0);
    // 5: HT = (h @ Wh^T)^T  (transOut, hi only; 2-term: s-path)
    gemm_split<2><<<gBig, 256, SMEM_GEMM>>>(hhi, hlo, Whh, nullptr, nullptr,
                                            nullptr, HTh, nullptr,
                                            DD, DD, DD, DD, 1, 0, 0, 0, 0);
    // 6: W = qv_w^T @ kh_w  (transOut -> WT, hi only; 2-term, tiny)
    gemm_split<2><<<gW, 256, SMEM_GEMM>>>(qvTh, qvTl, khTh, nullptr, nullptr,
                                          nullptr, WTh, nullptr,
                                          DD, DD, DD, DD, 1, 0, 0, 0, 0);
    // 7: vW = v @ W  (1-term: logit path; hi output only)
    gemm_split<1><<<gBig, 256, SMEM_GEMM>>>(vzh, nullptr, WTh, nullptr, nullptr,
                                            nullptr, vWh, nullptr,
                                            DD, KVZ, DD, DD, 0, 0, 0, 0, 0);
    // 8: att = vW·h + t[k]  (1-term: logit path; h_mask==0 -> NEGV)
    gemm_split<1><<<gBat, 256, SMEM_GEMM>>>(vWh, nullptr, hhi, T, h_mask,
                                            Att, nullptr, nullptr,
                                            DD, DD, DD, NVV, 0, PB, PB, PB, NVV);
    // 9: softmax -> split-fp16 P
    softmax_split_kernel<<<MROWS, 256>>>(Att, Ph, Pl);
    // 10: Hv = P @ HT^T  (2-term: s-path)
    gemm_split<2><<<gBat, 256, SMEM_GEMM>>>(Ph, Pl, HTh, nullptr, nullptr,
                                            Hv, nullptr, nullptr,
                                            NVV, NVV, NVV, DD, 0, PB, PB, PB, 0);

    // ---- tail ----
    su_kernel<<<MROWS, 256>>>(VZ, Hv, Wu_w, zout, U);
    p_kernel<<<BB, 256>>>(U, v_mask, P);
    g_kernel<<<dim3(DD / 256, BB), 256>>>(P, v, G);
    bcast_kernel<<<(MROWS * DD) / 256, 256>>>(G, hnew, zout);
}